// round 2
// baseline (speedup 1.0000x reference)
#include <cuda_runtime.h>

#define BSZ 32
#define NSEQ 20
#define DIM 512
#define HID 512
#define G4 2048          // 4*HID
#define NOUT 7680        // NT*SEM
#define SEM 256
#define NPAIR 190
#define MROWS (BSZ*NPAIR)   // 6080
#define SB (NSEQ*BSZ*HID)   // one state plane

// ---------------- device scratch (no allocations allowed) ----------------
__device__ float g_wv[BSZ*NSEQ*DIM];          // masked word vectors [b][t][512]
__device__ float g_Xf[BSZ*NSEQ*G4];           // x @ W_ih_f^T + biases  [b][t][2048]
__device__ float g_Xb[BSZ*NSEQ*G4];
__device__ float g_state[4*SB];               // Hf | Hb | Cf | Cb, each [chain][b][512]
__device__ float g_Gf[NSEQ*BSZ*G4];           // recurrent gate pre-activations (fwd)
__device__ float g_Gb[NSEQ*BSZ*G4];
__device__ float g_Ff[BSZ*NSEQ*NSEQ*HID];     // cumulative fwd hidden sums [b][s][e][512]
__device__ float g_Fb[BSZ*NSEQ*NSEQ*HID];     // cumulative bwd hidden sums [b][e][s][512]
__device__ int   g_psF[NPAIR];
__device__ int   g_psB[NPAIR];
__device__ int   g_pcnt[NPAIR];

__device__ __forceinline__ float sigm(float x){ return 1.f/(1.f+__expf(-x)); }

// ---------------- small setup kernels ----------------
__global__ void zero_state_kernel(){
  int i = blockIdx.x*blockDim.x + threadIdx.x;
  if (i < 4*SB) g_state[i] = 0.f;
}

__global__ void setup_pairs_kernel(){
  int p = threadIdx.x;
  if (p >= NPAIR) return;
  int cum = 0, k = 1, s = 0;
  for (int kk = 1; kk < NSEQ; kk++){
    int c = NSEQ - kk;
    if (p < cum + c){ k = kk; s = p - cum; break; }
    cum += c;
  }
  int e = s + k;
  g_psF[p] = s*NSEQ + e;
  g_psB[p] = e*NSEQ + s;
  g_pcnt[p] = k + 1;
}

__global__ void embed_kernel(const int* __restrict__ cap, const int* __restrict__ len,
                             const float* __restrict__ emb){
  int bt = blockIdx.x; int b = bt/NSEQ, t = bt%NSEQ;
  int tok = cap[bt];
  float m = (t < len[b]) ? 1.f : 0.f;
  const float* src = emb + (size_t)tok*DIM;
  for (int n = threadIdx.x; n < DIM; n += blockDim.x)
    g_wv[bt*DIM + n] = m * src[n];
}

// ---------------- generic tiled SGEMM: C = A(MxK) * B(NxK)^T + b1 + b2 ----------------
template<int BM,int BN,int BK,int TM,int TN>
__global__ void gemm_nt(const float* __restrict__ A, const float* __restrict__ B,
                        const float* __restrict__ b1, const float* __restrict__ b2,
                        float* __restrict__ C, int M, int N, int K)
{
  constexpr int THREADS = (BM/TM)*(BN/TN);
  __shared__ float As[BK][BM+1];
  __shared__ float Bs[BK][BN+1];
  int tid = threadIdx.x;
  int bm = blockIdx.y*BM, bn = blockIdx.x*BN;
  if (bm >= M) return;
  int tx = tid % (BN/TN), ty = tid / (BN/TN);
  float acc[TM][TN] = {};
  for (int k0 = 0; k0 < K; k0 += BK){
    #pragma unroll
    for (int i = tid; i < BM*BK; i += THREADS){
      int m = i / BK, k = i % BK;
      int gm = bm + m;
      As[k][m] = (gm < M) ? A[(size_t)gm*K + k0 + k] : 0.f;
    }
    #pragma unroll
    for (int i = tid; i < BN*BK; i += THREADS){
      int n = i / BK, k = i % BK;
      int gn = bn + n;
      Bs[k][n] = (gn < N) ? B[(size_t)gn*K + k0 + k] : 0.f;
    }
    __syncthreads();
    #pragma unroll
    for (int k = 0; k < BK; k++){
      float ra[TM], rb[TN];
      #pragma unroll
      for (int i = 0; i < TM; i++) ra[i] = As[k][ty*TM + i];
      #pragma unroll
      for (int j = 0; j < TN; j++) rb[j] = Bs[k][tx*TN + j];
      #pragma unroll
      for (int i = 0; i < TM; i++)
        #pragma unroll
        for (int j = 0; j < TN; j++) acc[i][j] += ra[i]*rb[j];
    }
    __syncthreads();
  }
  #pragma unroll
  for (int i = 0; i < TM; i++){
    int gm = bm + ty*TM + i; if (gm >= M) continue;
    #pragma unroll
    for (int j = 0; j < TN; j++){
      int gn = bn + tx*TN + j; if (gn >= N) continue;
      float v = acc[i][j];
      if (b1) v += b1[gn];
      if (b2) v += b2[gn];
      C[(size_t)gm*N + gn] = v;
    }
  }
}

// ---------------- recurrent GEMM: G = H_active @ W_hh^T (both directions via z) ----------------
__global__ void lstm_gemm(int j, const float* __restrict__ Wf, const float* __restrict__ Wb)
{
  constexpr int BM=64, BN=64, BK=16, TM=4, TN=4, THREADS=256;
  const float* A; const float* B; float* C; int M;
  if (blockIdx.z == 0){ A = g_state;                    B = Wf; C = g_Gf;                      M = (j+1)*BSZ; }
  else                { A = g_state + SB + j*BSZ*HID;   B = Wb; C = g_Gb + (size_t)j*BSZ*G4;   M = (NSEQ-j)*BSZ; }
  int bm = blockIdx.y*BM, bn = blockIdx.x*BN;
  if (bm >= M) return;
  __shared__ float As[BK][BM+1];
  __shared__ float Bs[BK][BN+1];
  int tid = threadIdx.x;
  int tx = tid % (BN/TN), ty = tid / (BN/TN);
  float acc[TM][TN] = {};
  for (int k0 = 0; k0 < HID; k0 += BK){
    #pragma unroll
    for (int i = tid; i < BM*BK; i += THREADS){
      int m = i / BK, k = i % BK;
      int gm = bm + m;
      As[k][m] = (gm < M) ? A[(size_t)gm*HID + k0 + k] : 0.f;
    }
    #pragma unroll
    for (int i = tid; i < BN*BK; i += THREADS){
      int n = i / BK, k = i % BK;
      Bs[k][n] = B[(size_t)(bn + n)*HID + k0 + k];
    }
    __syncthreads();
    #pragma unroll
    for (int k = 0; k < BK; k++){
      float ra[TM], rb[TN];
      #pragma unroll
      for (int i = 0; i < TM; i++) ra[i] = As[k][ty*TM + i];
      #pragma unroll
      for (int jj = 0; jj < TN; jj++) rb[jj] = Bs[k][tx*TN + jj];
      #pragma unroll
      for (int i = 0; i < TM; i++)
        #pragma unroll
        for (int jj = 0; jj < TN; jj++) acc[i][jj] += ra[i]*rb[jj];
    }
    __syncthreads();
  }
  #pragma unroll
  for (int i = 0; i < TM; i++){
    int gm = bm + ty*TM + i; if (gm >= M) continue;
    #pragma unroll
    for (int jj = 0; jj < TN; jj++){
      int gn = bn + tx*TN + jj;
      C[(size_t)gm*G4 + gn] = acc[i][jj];
    }
  }
}

// ---------------- gate nonlinearity + state update + cumulative hidden sums ----------------
__global__ void lstm_gate(int j)
{
  int blk = blockIdx.x;          // 0..671  (21*32 always)
  int n = threadIdx.x;           // 0..511
  int nf = (j+1)*BSZ;
  bool fwd = (blk < nf);
  int r, t;
  const float* X; const float* G; float* Hst; float* Cst;
  if (fwd){
    r = blk; t = j;
    X = g_Xf; G = g_Gf; Hst = g_state; Cst = g_state + 2*SB;
  } else {
    r = j*BSZ + (blk - nf);
    int e = r / BSZ; t = e - j;
    X = g_Xb; G = g_Gb; Hst = g_state + SB; Cst = g_state + 3*SB;
  }
  int b = r % BSZ;
  size_t gbase = (size_t)r*G4;
  size_t xbase = (size_t)(b*NSEQ + t)*G4;
  float gi = G[gbase + n]        + X[xbase + n];
  float gf = G[gbase + 512 + n]  + X[xbase + 512 + n];
  float gc = G[gbase + 1024 + n] + X[xbase + 1024 + n];
  float go = G[gbase + 1536 + n] + X[xbase + 1536 + n];
  float c = sigm(gf)*Cst[(size_t)r*HID + n] + sigm(gi)*tanhf(gc);
  float h = sigm(go)*tanhf(c);
  Cst[(size_t)r*HID + n] = c;
  Hst[(size_t)r*HID + n] = h;
  if (fwd){
    int s = r / BSZ;
    size_t idx = ((size_t)(b*NSEQ + s)*NSEQ + j)*HID + n;
    g_Ff[idx] = (j == s ? 0.f : g_Ff[idx - HID]) + h;
  } else {
    int e = r / BSZ;
    size_t idx = ((size_t)(b*NSEQ + e)*NSEQ + t)*HID + n;
    g_Fb[idx] = (t == e ? 0.f : g_Fb[idx + HID]) + h;
  }
}

// ---------------- final projection: per-pair gathered GEMM, K = 512(Ff) + 512(Fb) ----------------
__global__ void out_gemm(const float* __restrict__ Wout, const float* __restrict__ bout,
                         float* __restrict__ out)
{
  constexpr int BM=64, BN=64, BK=16, TM=4, TN=4, THREADS=256;
  __shared__ float As[BK][BM+1];
  __shared__ float Bs[BK][BN+1];
  __shared__ int offF[BM]; __shared__ int offB[BM]; __shared__ int cnt[BM];
  int tid = threadIdx.x;
  int bm = blockIdx.y*BM, bn = blockIdx.x*BN;
  if (tid < BM){
    int gm = bm + tid;
    int b = gm / NPAIR, p = gm % NPAIR;
    offF[tid] = (b*NSEQ*NSEQ + g_psF[p])*HID;
    offB[tid] = (b*NSEQ*NSEQ + g_psB[p])*HID;
    cnt[tid]  = g_pcnt[p];
  }
  __syncthreads();
  int tx = tid % (BN/TN), ty = tid / (BN/TN);
  float acc[TM][TN] = {};
  for (int k0 = 0; k0 < 2*HID; k0 += BK){
    #pragma unroll
    for (int i = tid; i < BM*BK; i += THREADS){
      int m = i / BK, k = i % BK;
      int gk = k0 + k;
      As[k][m] = (gk < HID) ? g_Ff[offF[m] + gk] : g_Fb[offB[m] + gk - HID];
    }
    #pragma unroll
    for (int i = tid; i < BN*BK; i += THREADS){
      int n = i / BK, k = i % BK;
      Bs[k][n] = Wout[(size_t)(bn + n)*(2*HID) + k0 + k];
    }
    __syncthreads();
    #pragma unroll
    for (int k = 0; k < BK; k++){
      float ra[TM], rb[TN];
      #pragma unroll
      for (int i = 0; i < TM; i++) ra[i] = As[k][ty*TM + i];
      #pragma unroll
      for (int jj = 0; jj < TN; jj++) rb[jj] = Bs[k][tx*TN + jj];
      #pragma unroll
      for (int i = 0; i < TM; i++)
        #pragma unroll
        for (int jj = 0; jj < TN; jj++) acc[i][jj] += ra[i]*rb[jj];
    }
    __syncthreads();
  }
  #pragma unroll
  for (int i = 0; i < TM; i++){
    int gm = bm + ty*TM + i;
    #pragma unroll
    for (int jj = 0; jj < TN; jj++){
      int gn = bn + tx*TN + jj;
      out[(size_t)gm*NOUT + gn] = acc[i][jj] + (float)cnt[ty*TM + i]*bout[gn];
    }
  }
}

// ---------------- L2 normalize each (row, nt) group of 256 in place ----------------
__global__ void normalize_kernel(float* __restrict__ out)
{
  int w = blockIdx.x*8 + (threadIdx.x >> 5);
  int lane = threadIdx.x & 31;
  size_t base = (size_t)w*SEM;
  float v[8]; float ss = 0.f;
  #pragma unroll
  for (int i = 0; i < 8; i++){ v[i] = out[base + lane + 32*i]; ss += v[i]*v[i]; }
  #pragma unroll
  for (int o = 16; o; o >>= 1) ss += __shfl_xor_sync(0xffffffffu, ss, o);
  float sc = 1.f / fmaxf(sqrtf(ss), 1e-12f);
  #pragma unroll
  for (int i = 0; i < 8; i++) out[base + lane + 32*i] = v[i]*sc;
}

// ---------------- launcher ----------------
extern "C" void kernel_launch(void* const* d_in, const int* in_sizes, int n_in,
                              void* d_out, int out_size)
{
  const int*   captions = (const int*)  d_in[1];
  const int*   lengths  = (const int*)  d_in[2];
  const float* emb      = (const float*)d_in[3];
  const float* w_ih_f   = (const float*)d_in[4];
  const float* w_hh_f   = (const float*)d_in[5];
  const float* b_ih_f   = (const float*)d_in[6];
  const float* b_hh_f   = (const float*)d_in[7];
  const float* w_ih_b   = (const float*)d_in[8];
  const float* w_hh_b   = (const float*)d_in[9];
  const float* b_ih_b   = (const float*)d_in[10];
  const float* b_hh_b   = (const float*)d_in[11];
  const float* w_out    = (const float*)d_in[12];
  const float* b_out    = (const float*)d_in[13];
  float* out = (float*)d_out;

  float *wv, *Xf, *Xb;
  cudaGetSymbolAddress((void**)&wv, g_wv);
  cudaGetSymbolAddress((void**)&Xf, g_Xf);
  cudaGetSymbolAddress((void**)&Xb, g_Xb);

  zero_state_kernel<<<(4*SB + 255)/256, 256>>>();
  setup_pairs_kernel<<<1, 256>>>();
  embed_kernel<<<BSZ*NSEQ, 256>>>(captions, lengths, emb);

  // input projections (bias folded in): X = wv @ W_ih^T + (b_ih + b_hh)
  gemm_nt<64,64,16,4,4><<<dim3(G4/64, (BSZ*NSEQ + 63)/64), 256>>>(
      wv, w_ih_f, b_ih_f, b_hh_f, Xf, BSZ*NSEQ, G4, DIM);
  gemm_nt<64,64,16,4,4><<<dim3(G4/64, (BSZ*NSEQ + 63)/64), 256>>>(
      wv, w_ih_b, b_ih_b, b_hh_b, Xb, BSZ*NSEQ, G4, DIM);

  // 20 global steps; forward chains s<=j process position j, backward chains e>=j process e-j
  for (int j = 0; j < NSEQ; j++){
    lstm_gemm<<<dim3(G4/64, (NSEQ*BSZ + 63)/64, 2), 256>>>(j, w_hh_f, w_hh_b);
    lstm_gate<<<(NSEQ+1)*BSZ, 512>>>(j);
  }

  // final projection over all 6080 (b,s,e) pairs + per-group normalize
  out_gemm<<<dim3(NOUT/64, MROWS/64), 256>>>(w_out, b_out, out);
  normalize_kernel<<<(MROWS*30)/8, 256>>>(out);
}

// round 3
// speedup vs baseline: 3.2348x; 3.2348x over previous
#include <cuda_runtime.h>
#include <stdint.h>

#define BSZ 32
#define NSEQ 20
#define DIM 512
#define HID 512
#define G4 2048          // 4*HID
#define NOUT 7680        // NT*SEM
#define SEM 256
#define NPAIR 190
#define MROWS (BSZ*NPAIR)   // 6080
#define SB (NSEQ*BSZ*HID)   // one state plane

// ---------------- device scratch ----------------
__device__ float g_wv[BSZ*NSEQ*DIM];
__device__ float g_Xf[BSZ*NSEQ*G4];
__device__ float g_Xb[BSZ*NSEQ*G4];
__device__ float g_state[4*SB];               // Hf | Hb | Cf | Cb
__device__ float g_Gf[NSEQ*BSZ*G4];
__device__ float g_Gb[NSEQ*BSZ*G4];
__device__ float g_Ff[BSZ*NSEQ*NSEQ*HID];
__device__ float g_Fb[BSZ*NSEQ*NSEQ*HID];
__device__ int   g_psF[NPAIR];
__device__ int   g_psB[NPAIR];
__device__ int   g_pcnt[NPAIR];

__device__ __forceinline__ float sigm(float x){ return 1.f/(1.f+__expf(-x)); }

__device__ __forceinline__ uint32_t f2tf(float x){
  uint32_t r; asm("cvt.rna.tf32.f32 %0, %1;" : "=r"(r) : "f"(x)); return r;
}
__device__ __forceinline__ void mma8(float c[4], const uint32_t a[4], const uint32_t b[2]){
  asm volatile("mma.sync.aligned.m16n8k8.row.col.f32.tf32.tf32.f32 "
      "{%0,%1,%2,%3}, {%4,%5,%6,%7}, {%8,%9}, {%0,%1,%2,%3};\n"
      : "+f"(c[0]), "+f"(c[1]), "+f"(c[2]), "+f"(c[3])
      : "r"(a[0]), "r"(a[1]), "r"(a[2]), "r"(a[3]), "r"(b[0]), "r"(b[1]));
}

// ---------------- small setup kernels ----------------
__global__ void zero_state_kernel(){
  int i = blockIdx.x*blockDim.x + threadIdx.x;
  if (i < 4*SB) g_state[i] = 0.f;
}

__global__ void setup_pairs_kernel(){
  int p = threadIdx.x;
  if (p >= NPAIR) return;
  int cum = 0, k = 1, s = 0;
  for (int kk = 1; kk < NSEQ; kk++){
    int c = NSEQ - kk;
    if (p < cum + c){ k = kk; s = p - cum; break; }
    cum += c;
  }
  int e = s + k;
  g_psF[p] = s*NSEQ + e;
  g_psB[p] = e*NSEQ + s;
  g_pcnt[p] = k + 1;
}

__global__ void embed_kernel(const int* __restrict__ cap, const int* __restrict__ len,
                             const float* __restrict__ emb){
  int bt = blockIdx.x; int b = bt/NSEQ, t = bt%NSEQ;
  int tok = cap[bt];
  float m = (t < len[b]) ? 1.f : 0.f;
  const float* src = emb + (size_t)tok*DIM;
  for (int n = threadIdx.x; n < DIM; n += blockDim.x)
    g_wv[bt*DIM + n] = m * src[n];
}

// =======================================================================
// 3xTF32 GEMM core: C[M x N] = A[M x K] @ B[N x K]^T (+ b1 + b2)
// BM=64, BN=128, BK=16, 256 threads = 8 warps (2 M x 4 N), warp tile 32x32
// =======================================================================
struct S3x {
  uint32_t Ah[64][20]; uint32_t Al[64][20];
  uint32_t Bh[128][20]; uint32_t Bl[128][20];
};

__device__ __forceinline__ void gemm3x_core(
    const float* __restrict__ A, const float* __restrict__ B,
    const float* __restrict__ b1, const float* __restrict__ b2,
    float* __restrict__ C, int M, int N, int K, int bm, int bn, S3x& s)
{
  int tid = threadIdx.x;
  int lane = tid & 31, wid = tid >> 5;
  int warpM = wid >> 2, warpN = wid & 3;
  int g = lane >> 2, t = lane & 3;
  float acc[2][4][4] = {};

  for (int k0 = 0; k0 < K; k0 += 16){
    // ---- A tile 64x16 (4 floats / thread) ----
    int ar = tid >> 2, ak = (tid & 3) * 4;
    int gm = bm + ar;
    float4 av = make_float4(0.f,0.f,0.f,0.f);
    if (gm < M) av = *(const float4*)(A + (size_t)gm*K + k0 + ak);
    // ---- B tile 128x16 (8 floats / thread) ----
    float4 bv[2];
    #pragma unroll
    for (int i = 0; i < 2; i++){
      int idx = tid + i*256;
      int br = idx >> 2, bk = (idx & 3) * 4;
      bv[i] = *(const float4*)(B + (size_t)(bn + br)*K + k0 + bk);
    }
    __syncthreads();
    {
      uint32_t h0=f2tf(av.x), h1=f2tf(av.y), h2=f2tf(av.z), h3=f2tf(av.w);
      s.Ah[ar][ak]=h0; s.Ah[ar][ak+1]=h1; s.Ah[ar][ak+2]=h2; s.Ah[ar][ak+3]=h3;
      s.Al[ar][ak]  =f2tf(av.x-__uint_as_float(h0));
      s.Al[ar][ak+1]=f2tf(av.y-__uint_as_float(h1));
      s.Al[ar][ak+2]=f2tf(av.z-__uint_as_float(h2));
      s.Al[ar][ak+3]=f2tf(av.w-__uint_as_float(h3));
    }
    #pragma unroll
    for (int i = 0; i < 2; i++){
      int idx = tid + i*256;
      int br = idx >> 2, bk = (idx & 3) * 4;
      uint32_t h0=f2tf(bv[i].x), h1=f2tf(bv[i].y), h2=f2tf(bv[i].z), h3=f2tf(bv[i].w);
      s.Bh[br][bk]=h0; s.Bh[br][bk+1]=h1; s.Bh[br][bk+2]=h2; s.Bh[br][bk+3]=h3;
      s.Bl[br][bk]  =f2tf(bv[i].x-__uint_as_float(h0));
      s.Bl[br][bk+1]=f2tf(bv[i].y-__uint_as_float(h1));
      s.Bl[br][bk+2]=f2tf(bv[i].z-__uint_as_float(h2));
      s.Bl[br][bk+3]=f2tf(bv[i].w-__uint_as_float(h3));
    }
    __syncthreads();
    #pragma unroll
    for (int ks = 0; ks < 16; ks += 8){
      uint32_t ah[2][4], al[2][4], bh[4][2], bl[4][2];
      #pragma unroll
      for (int mt = 0; mt < 2; mt++){
        int m = warpM*32 + mt*16 + g;
        int k = ks + t;
        ah[mt][0]=s.Ah[m][k];   ah[mt][1]=s.Ah[m+8][k];
        ah[mt][2]=s.Ah[m][k+4]; ah[mt][3]=s.Ah[m+8][k+4];
        al[mt][0]=s.Al[m][k];   al[mt][1]=s.Al[m+8][k];
        al[mt][2]=s.Al[m][k+4]; al[mt][3]=s.Al[m+8][k+4];
      }
      #pragma unroll
      for (int nt = 0; nt < 4; nt++){
        int n = warpN*32 + nt*8 + g;
        bh[nt][0]=s.Bh[n][ks+t]; bh[nt][1]=s.Bh[n][ks+t+4];
        bl[nt][0]=s.Bl[n][ks+t]; bl[nt][1]=s.Bl[n][ks+t+4];
      }
      #pragma unroll
      for (int mt = 0; mt < 2; mt++)
        #pragma unroll
        for (int nt = 0; nt < 4; nt++){
          mma8(acc[mt][nt], ah[mt], bh[nt]);
          mma8(acc[mt][nt], al[mt], bh[nt]);
          mma8(acc[mt][nt], ah[mt], bl[nt]);
        }
    }
    __syncthreads();
  }
  // ---- epilogue ----
  #pragma unroll
  for (int mt = 0; mt < 2; mt++){
    int r0 = bm + warpM*32 + mt*16 + g;
    #pragma unroll
    for (int nt = 0; nt < 4; nt++){
      int gn = bn + warpN*32 + nt*8 + 2*t;
      float e0 = 0.f, e1 = 0.f;
      if (b1){ e0 = b1[gn] + b2[gn]; e1 = b1[gn+1] + b2[gn+1]; }
      if (r0 < M){
        C[(size_t)r0*N + gn]     = acc[mt][nt][0] + e0;
        C[(size_t)r0*N + gn + 1] = acc[mt][nt][1] + e1;
      }
      if (r0 + 8 < M){
        C[(size_t)(r0+8)*N + gn]     = acc[mt][nt][2] + e0;
        C[(size_t)(r0+8)*N + gn + 1] = acc[mt][nt][3] + e1;
      }
    }
  }
}

__global__ void gemm3x_bias(const float* __restrict__ A, const float* __restrict__ B,
                            const float* __restrict__ b1, const float* __restrict__ b2,
                            float* __restrict__ C, int M, int N, int K)
{
  __shared__ S3x s;
  gemm3x_core(A, B, b1, b2, C, M, N, K, blockIdx.y*64, blockIdx.x*128, s);
}

__global__ void lstm_gemm3x(int j, const float* __restrict__ Wf, const float* __restrict__ Wb)
{
  __shared__ S3x s;
  const float* A; const float* B; float* C; int M;
  if (blockIdx.z == 0){ A = g_state;                  B = Wf; C = g_Gf;                      M = (j+1)*BSZ; }
  else                { A = g_state + SB + j*BSZ*HID; B = Wb; C = g_Gb + (size_t)j*BSZ*G4;   M = (NSEQ-j)*BSZ; }
  int bm = blockIdx.y*64;
  if (bm >= M) return;
  gemm3x_core(A, B, nullptr, nullptr, C, M, G4, HID, bm, blockIdx.x*128, s);
}

// ---------------- gate nonlinearity + state update + cumulative sums ----------------
__global__ void lstm_gate(int j)
{
  int blk = blockIdx.x;
  int n = threadIdx.x;
  int nf = (j+1)*BSZ;
  bool fwd = (blk < nf);
  int r, t;
  const float* X; const float* G; float* Hst; float* Cst;
  if (fwd){
    r = blk; t = j;
    X = g_Xf; G = g_Gf; Hst = g_state; Cst = g_state + 2*SB;
  } else {
    r = j*BSZ + (blk - nf);
    int e = r / BSZ; t = e - j;
    X = g_Xb; G = g_Gb; Hst = g_state + SB; Cst = g_state + 3*SB;
  }
  int b = r % BSZ;
  size_t gbase = (size_t)r*G4;
  size_t xbase = (size_t)(b*NSEQ + t)*G4;
  float gi = G[gbase + n]        + X[xbase + n];
  float gf = G[gbase + 512 + n]  + X[xbase + 512 + n];
  float gc = G[gbase + 1024 + n] + X[xbase + 1024 + n];
  float go = G[gbase + 1536 + n] + X[xbase + 1536 + n];
  float c = sigm(gf)*Cst[(size_t)r*HID + n] + sigm(gi)*tanhf(gc);
  float h = sigm(go)*tanhf(c);
  Cst[(size_t)r*HID + n] = c;
  Hst[(size_t)r*HID + n] = h;
  if (fwd){
    int s = r / BSZ;
    size_t idx = ((size_t)(b*NSEQ + s)*NSEQ + j)*HID + n;
    g_Ff[idx] = (j == s ? 0.f : g_Ff[idx - HID]) + h;
  } else {
    int e = r / BSZ;
    size_t idx = ((size_t)(b*NSEQ + e)*NSEQ + t)*HID + n;
    g_Fb[idx] = (t == e ? 0.f : g_Fb[idx + HID]) + h;
  }
}

// =======================================================================
// out GEMM: single-pass TF32. M=6080 (gathered rows), N=7680, K=1024
// BM=128, BN=128, BK=16, 256 thr = 8 warps (2 M x 4 N), warp tile 64x32
// =======================================================================
__global__ void out_gemm_mma(const float* __restrict__ Wout, const float* __restrict__ bout,
                             float* __restrict__ out)
{
  __shared__ uint32_t As[128][20];
  __shared__ uint32_t Bs[128][20];
  __shared__ int offF[128], offB[128], cnt[128];
  int tid = threadIdx.x, lane = tid & 31, wid = tid >> 5;
  int warpM = wid >> 2, warpN = wid & 3;
  int g = lane >> 2, t = lane & 3;
  int bm = blockIdx.y*128, bn = blockIdx.x*128;

  if (tid < 128){
    int gm = bm + tid;
    if (gm < MROWS){
      int b = gm / NPAIR, p = gm % NPAIR;
      offF[tid] = (b*NSEQ*NSEQ + g_psF[p])*HID;
      offB[tid] = (b*NSEQ*NSEQ + g_psB[p])*HID;
      cnt[tid]  = g_pcnt[p];
    } else { offF[tid] = 0; offB[tid] = 0; cnt[tid] = 0; }
  }
  __syncthreads();

  float acc[4][4][4] = {};
  for (int k0 = 0; k0 < 2*HID; k0 += 16){
    float4 av[2], bv[2];
    #pragma unroll
    for (int i = 0; i < 2; i++){
      int idx = tid + i*256;
      int m = idx >> 2, kg = (idx & 3) * 4;
      int k = k0 + kg;
      const float* src = (k < HID) ? (g_Ff + offF[m] + k) : (g_Fb + offB[m] + k - HID);
      av[i] = *(const float4*)src;
      int nn = idx >> 2;
      bv[i] = *(const float4*)(Wout + (size_t)(bn + nn)*(2*HID) + k0 + kg);
    }
    __syncthreads();
    #pragma unroll
    for (int i = 0; i < 2; i++){
      int idx = tid + i*256;
      int m = idx >> 2, kg = (idx & 3) * 4;
      As[m][kg]=f2tf(av[i].x); As[m][kg+1]=f2tf(av[i].y);
      As[m][kg+2]=f2tf(av[i].z); As[m][kg+3]=f2tf(av[i].w);
      Bs[m][kg]=f2tf(bv[i].x); Bs[m][kg+1]=f2tf(bv[i].y);
      Bs[m][kg+2]=f2tf(bv[i].z); Bs[m][kg+3]=f2tf(bv[i].w);
    }
    __syncthreads();
    #pragma unroll
    for (int ks = 0; ks < 16; ks += 8){
      uint32_t a[4][4], b[4][2];
      #pragma unroll
      for (int mt = 0; mt < 4; mt++){
        int m = warpM*64 + mt*16 + g;
        int k = ks + t;
        a[mt][0]=As[m][k];   a[mt][1]=As[m+8][k];
        a[mt][2]=As[m][k+4]; a[mt][3]=As[m+8][k+4];
      }
      #pragma unroll
      for (int nt = 0; nt < 4; nt++){
        int n = warpN*32 + nt*8 + g;
        b[nt][0]=Bs[n][ks+t]; b[nt][1]=Bs[n][ks+t+4];
      }
      #pragma unroll
      for (int mt = 0; mt < 4; mt++)
        #pragma unroll
        for (int nt = 0; nt < 4; nt++)
          mma8(acc[mt][nt], a[mt], b[nt]);
    }
    __syncthreads();
  }
  // epilogue: + cnt * bias
  #pragma unroll
  for (int mt = 0; mt < 4; mt++){
    int r0 = warpM*64 + mt*16 + g;      // local row
    int gm0 = bm + r0;
    float c0 = (float)cnt[r0], c1 = (float)cnt[r0+8];
    #pragma unroll
    for (int nt = 0; nt < 4; nt++){
      int gn = bn + warpN*32 + nt*8 + 2*t;
      float bb0 = bout[gn], bb1 = bout[gn+1];
      if (gm0 < MROWS){
        out[(size_t)gm0*NOUT + gn]     = acc[mt][nt][0] + c0*bb0;
        out[(size_t)gm0*NOUT + gn + 1] = acc[mt][nt][1] + c0*bb1;
      }
      if (gm0 + 8 < MROWS){
        out[(size_t)(gm0+8)*NOUT + gn]     = acc[mt][nt][2] + c1*bb0;
        out[(size_t)(gm0+8)*NOUT + gn + 1] = acc[mt][nt][3] + c1*bb1;
      }
    }
  }
}

// ---------------- L2 normalize groups of 256 ----------------
__global__ void normalize_kernel(float* __restrict__ out)
{
  int w = blockIdx.x*8 + (threadIdx.x >> 5);
  int lane = threadIdx.x & 31;
  size_t base = (size_t)w*SEM;
  float v[8]; float ss = 0.f;
  #pragma unroll
  for (int i = 0; i < 8; i++){ v[i] = out[base + lane + 32*i]; ss += v[i]*v[i]; }
  #pragma unroll
  for (int o = 16; o; o >>= 1) ss += __shfl_xor_sync(0xffffffffu, ss, o);
  float sc = 1.f / fmaxf(sqrtf(ss), 1e-12f);
  #pragma unroll
  for (int i = 0; i < 8; i++) out[base + lane + 32*i] = v[i]*sc;
}

// ---------------- launcher ----------------
extern "C" void kernel_launch(void* const* d_in, const int* in_sizes, int n_in,
                              void* d_out, int out_size)
{
  const int*   captions = (const int*)  d_in[1];
  const int*   lengths  = (const int*)  d_in[2];
  const float* emb      = (const float*)d_in[3];
  const float* w_ih_f   = (const float*)d_in[4];
  const float* w_hh_f   = (const float*)d_in[5];
  const float* b_ih_f   = (const float*)d_in[6];
  const float* b_hh_f   = (const float*)d_in[7];
  const float* w_ih_b   = (const float*)d_in[8];
  const float* w_hh_b   = (const float*)d_in[9];
  const float* b_ih_b   = (const float*)d_in[10];
  const float* b_hh_b   = (const float*)d_in[11];
  const float* w_out    = (const float*)d_in[12];
  const float* b_out    = (const float*)d_in[13];
  float* out = (float*)d_out;

  float *wv, *Xf, *Xb;
  cudaGetSymbolAddress((void**)&wv, g_wv);
  cudaGetSymbolAddress((void**)&Xf, g_Xf);
  cudaGetSymbolAddress((void**)&Xb, g_Xb);

  zero_state_kernel<<<(4*SB + 255)/256, 256>>>();
  setup_pairs_kernel<<<1, 256>>>();
  embed_kernel<<<BSZ*NSEQ, 256>>>(captions, lengths, emb);

  // input projections: X = wv @ W_ih^T + (b_ih + b_hh)   (3xTF32)
  gemm3x_bias<<<dim3(G4/128, (BSZ*NSEQ + 63)/64), 256>>>(
      wv, w_ih_f, b_ih_f, b_hh_f, Xf, BSZ*NSEQ, G4, DIM);
  gemm3x_bias<<<dim3(G4/128, (BSZ*NSEQ + 63)/64), 256>>>(
      wv, w_ih_b, b_ih_b, b_hh_b, Xb, BSZ*NSEQ, G4, DIM);

  // 20 global steps (3xTF32 recurrent GEMM + fused gates)
  for (int j = 0; j < NSEQ; j++){
    lstm_gemm3x<<<dim3(G4/128, 10, 2), 256>>>(j, w_hh_f, w_hh_b);
    lstm_gate<<<(NSEQ+1)*BSZ, 512>>>(j);
  }

  // final projection (single-pass TF32) + per-group normalize
  out_gemm_mma<<<dim3(NOUT/128, (MROWS + 127)/128), 256>>>(w_out, b_out, out);
  normalize_kernel<<<(MROWS*30)/8, 256>>>(out);
}

// round 4
// speedup vs baseline: 3.3357x; 1.0312x over previous
#include <cuda_runtime.h>
#include <cuda_bf16.h>
#include <stdint.h>

#define BSZ 32
#define NSEQ 20
#define DIM 512
#define HID 512
#define G4 2048          // 4*HID
#define NOUT 7680        // NT*SEM
#define SEM 256
#define NPAIR 190
#define MROWS (BSZ*NPAIR)   // 6080
#define SB (NSEQ*BSZ*HID)   // 640*512 per plane

// ---------------- device scratch ----------------
__device__ float g_wv[BSZ*NSEQ*DIM];
__device__ float g_X[2][BSZ*NSEQ*G4];          // input projections (f, b)
__device__ __nv_bfloat16 g_Hh[2][2][SB];       // [dir][parity] hidden hi
__device__ __nv_bfloat16 g_Hl[2][2][SB];       // [dir][parity] hidden lo
__device__ float g_C[2][SB];                   // cell state
__device__ __nv_bfloat16 g_Wh[2][G4*HID];      // W_hh hi (f, b)
__device__ __nv_bfloat16 g_Wl[2][G4*HID];      // W_hh lo
__device__ float g_Ff[BSZ*NSEQ*NSEQ*HID];
__device__ float g_Fb[BSZ*NSEQ*NSEQ*HID];
__device__ int   g_psF[NPAIR];
__device__ int   g_psB[NPAIR];
__device__ int   g_pcnt[NPAIR];

__device__ __forceinline__ float sigm(float x){ return 1.f/(1.f+__expf(-x)); }

__device__ __forceinline__ uint32_t f2tf(float x){
  uint32_t r; asm("cvt.rna.tf32.f32 %0, %1;" : "=r"(r) : "f"(x)); return r;
}
__device__ __forceinline__ void mma8(float c[4], const uint32_t a[4], const uint32_t b[2]){
  asm volatile("mma.sync.aligned.m16n8k8.row.col.f32.tf32.tf32.f32 "
      "{%0,%1,%2,%3}, {%4,%5,%6,%7}, {%8,%9}, {%0,%1,%2,%3};\n"
      : "+f"(c[0]), "+f"(c[1]), "+f"(c[2]), "+f"(c[3])
      : "r"(a[0]), "r"(a[1]), "r"(a[2]), "r"(a[3]), "r"(b[0]), "r"(b[1]));
}
__device__ __forceinline__ void mma16(float c[4], const uint32_t a[4], const uint32_t b[2]){
  asm volatile("mma.sync.aligned.m16n8k16.row.col.f32.bf16.bf16.f32 "
      "{%0,%1,%2,%3}, {%4,%5,%6,%7}, {%8,%9}, {%0,%1,%2,%3};\n"
      : "+f"(c[0]), "+f"(c[1]), "+f"(c[2]), "+f"(c[3])
      : "r"(a[0]), "r"(a[1]), "r"(a[2]), "r"(a[3]), "r"(b[0]), "r"(b[1]));
}

// ---------------- small setup kernels ----------------
__global__ void zero_state_kernel(){
  int i = blockIdx.x*blockDim.x + threadIdx.x;
  if (i < 4*SB){
    (&g_Hh[0][0][0])[i] = __float2bfloat16(0.f);
    (&g_Hl[0][0][0])[i] = __float2bfloat16(0.f);
  }
  if (i < 2*SB) (&g_C[0][0])[i] = 0.f;
}

__global__ void wsplit_kernel(const float* __restrict__ wf, const float* __restrict__ wb){
  int i = blockIdx.x*blockDim.x + threadIdx.x;
  if (i >= G4*HID) return;
  float w = wf[i];
  __nv_bfloat16 h = __float2bfloat16(w);
  g_Wh[0][i] = h;
  g_Wl[0][i] = __float2bfloat16(w - __bfloat162float(h));
  w = wb[i];
  h = __float2bfloat16(w);
  g_Wh[1][i] = h;
  g_Wl[1][i] = __float2bfloat16(w - __bfloat162float(h));
}

__global__ void setup_pairs_kernel(){
  int p = threadIdx.x;
  if (p >= NPAIR) return;
  int cum = 0, k = 1, s = 0;
  for (int kk = 1; kk < NSEQ; kk++){
    int c = NSEQ - kk;
    if (p < cum + c){ k = kk; s = p - cum; break; }
    cum += c;
  }
  int e = s + k;
  g_psF[p] = s*NSEQ + e;
  g_psB[p] = e*NSEQ + s;
  g_pcnt[p] = k + 1;
}

__global__ void embed_kernel(const int* __restrict__ cap, const int* __restrict__ len,
                             const float* __restrict__ emb){
  int bt = blockIdx.x; int b = bt/NSEQ, t = bt%NSEQ;
  int tok = cap[bt];
  float m = (t < len[b]) ? 1.f : 0.f;
  const float* src = emb + (size_t)tok*DIM;
  for (int n = threadIdx.x; n < DIM; n += blockDim.x)
    g_wv[bt*DIM + n] = m * src[n];
}

// =======================================================================
// 3xTF32 GEMM (input projections): C = A(MxK) @ B(NxK)^T + b1 + b2
// =======================================================================
struct S3x {
  uint32_t Ah[64][20]; uint32_t Al[64][20];
  uint32_t Bh[128][20]; uint32_t Bl[128][20];
};

__global__ void gemm3x_bias(const float* __restrict__ A, const float* __restrict__ B,
                            const float* __restrict__ b1, const float* __restrict__ b2,
                            float* __restrict__ C, int M, int N, int K)
{
  __shared__ S3x s;
  int tid = threadIdx.x;
  int lane = tid & 31, wid = tid >> 5;
  int warpM = wid >> 2, warpN = wid & 3;
  int g = lane >> 2, t = lane & 3;
  int bm = blockIdx.y*64, bn = blockIdx.x*128;
  if (bm >= M) return;
  float acc[2][4][4] = {};

  for (int k0 = 0; k0 < K; k0 += 16){
    int ar = tid >> 2, ak = (tid & 3) * 4;
    int gm = bm + ar;
    float4 av = make_float4(0.f,0.f,0.f,0.f);
    if (gm < M) av = *(const float4*)(A + (size_t)gm*K + k0 + ak);
    float4 bv[2];
    #pragma unroll
    for (int i = 0; i < 2; i++){
      int idx = tid + i*256;
      int br = idx >> 2, bk = (idx & 3) * 4;
      bv[i] = *(const float4*)(B + (size_t)(bn + br)*K + k0 + bk);
    }
    __syncthreads();
    {
      uint32_t h0=f2tf(av.x), h1=f2tf(av.y), h2=f2tf(av.z), h3=f2tf(av.w);
      s.Ah[ar][ak]=h0; s.Ah[ar][ak+1]=h1; s.Ah[ar][ak+2]=h2; s.Ah[ar][ak+3]=h3;
      s.Al[ar][ak]  =f2tf(av.x-__uint_as_float(h0));
      s.Al[ar][ak+1]=f2tf(av.y-__uint_as_float(h1));
      s.Al[ar][ak+2]=f2tf(av.z-__uint_as_float(h2));
      s.Al[ar][ak+3]=f2tf(av.w-__uint_as_float(h3));
    }
    #pragma unroll
    for (int i = 0; i < 2; i++){
      int idx = tid + i*256;
      int br = idx >> 2, bk = (idx & 3) * 4;
      uint32_t h0=f2tf(bv[i].x), h1=f2tf(bv[i].y), h2=f2tf(bv[i].z), h3=f2tf(bv[i].w);
      s.Bh[br][bk]=h0; s.Bh[br][bk+1]=h1; s.Bh[br][bk+2]=h2; s.Bh[br][bk+3]=h3;
      s.Bl[br][bk]  =f2tf(bv[i].x-__uint_as_float(h0));
      s.Bl[br][bk+1]=f2tf(bv[i].y-__uint_as_float(h1));
      s.Bl[br][bk+2]=f2tf(bv[i].z-__uint_as_float(h2));
      s.Bl[br][bk+3]=f2tf(bv[i].w-__uint_as_float(h3));
    }
    __syncthreads();
    #pragma unroll
    for (int ks = 0; ks < 16; ks += 8){
      uint32_t ah[2][4], al[2][4], bh[4][2], bl[4][2];
      #pragma unroll
      for (int mt = 0; mt < 2; mt++){
        int m = warpM*32 + mt*16 + g;
        int k = ks + t;
        ah[mt][0]=s.Ah[m][k];   ah[mt][1]=s.Ah[m+8][k];
        ah[mt][2]=s.Ah[m][k+4]; ah[mt][3]=s.Ah[m+8][k+4];
        al[mt][0]=s.Al[m][k];   al[mt][1]=s.Al[m+8][k];
        al[mt][2]=s.Al[m][k+4]; al[mt][3]=s.Al[m+8][k+4];
      }
      #pragma unroll
      for (int nt = 0; nt < 4; nt++){
        int n = warpN*32 + nt*8 + g;
        bh[nt][0]=s.Bh[n][ks+t]; bh[nt][1]=s.Bh[n][ks+t+4];
        bl[nt][0]=s.Bl[n][ks+t]; bl[nt][1]=s.Bl[n][ks+t+4];
      }
      #pragma unroll
      for (int mt = 0; mt < 2; mt++)
        #pragma unroll
        for (int nt = 0; nt < 4; nt++){
          mma8(acc[mt][nt], ah[mt], bh[nt]);
          mma8(acc[mt][nt], al[mt], bh[nt]);
          mma8(acc[mt][nt], ah[mt], bl[nt]);
        }
    }
    __syncthreads();
  }
  #pragma unroll
  for (int mt = 0; mt < 2; mt++){
    int r0 = bm + warpM*32 + mt*16 + g;
    #pragma unroll
    for (int nt = 0; nt < 4; nt++){
      int gn = bn + warpN*32 + nt*8 + 2*t;
      float e0 = b1[gn] + b2[gn], e1 = b1[gn+1] + b2[gn+1];
      if (r0 < M){
        C[(size_t)r0*N + gn]     = acc[mt][nt][0] + e0;
        C[(size_t)r0*N + gn + 1] = acc[mt][nt][1] + e1;
      }
      if (r0 + 8 < M){
        C[(size_t)(r0+8)*N + gn]     = acc[mt][nt][2] + e0;
        C[(size_t)(r0+8)*N + gn + 1] = acc[mt][nt][3] + e1;
      }
    }
  }
}

// =======================================================================
// Fused LSTM step: 3xBF16 recurrent GEMM + gates + state + F cumsum
// Block: 64 rows x 64 hidden cols (x4 gates).  8 warps: warpM in [0,4), warpN in [0,2)
// =======================================================================
__global__ void lstm_fused(int j)
{
  const int dir = blockIdx.z;
  const int n0 = blockIdx.x * 64;
  const int p = j & 1;
  int bm, rowLim;
  if (dir == 0){
    rowLim = (j+1)*BSZ;
    bm = blockIdx.y * 64;
    if (bm >= rowLim) return;
  } else {
    rowLim = NSEQ*BSZ;
    bm = j*BSZ + blockIdx.y*64;
    if (bm >= rowLim) return;
  }
  const __nv_bfloat16* __restrict__ Ah = g_Hh[dir][p];
  const __nv_bfloat16* __restrict__ Al = g_Hl[dir][p];
  const __nv_bfloat16* __restrict__ Wh = g_Wh[dir];
  const __nv_bfloat16* __restrict__ Wl = g_Wl[dir];

  __shared__ __align__(16) uint16_t sA[2][64][24];   // pad 8: conflict-free frags
  __shared__ __align__(16) uint16_t sB[2][256][24];

  const int tid = threadIdx.x, lane = tid & 31, wid = tid >> 5;
  const int warpM = wid & 3, warpN = wid >> 2;
  const int g8 = lane >> 2, t4 = lane & 3;

  float acc[4][4][4] = {};   // [gate][ntile][frag]

  uint4 ra[2]; uint4 rb[2][2];
  const int arow = tid >> 1, ak8 = (tid & 1)*8;      // A loader (tid<128)

  // prefetch k0=0
  {
    if (tid < 128){
      int gr = bm + arow;
      if (gr < rowLim){
        ra[0] = *(const uint4*)(Ah + (size_t)gr*HID + ak8);
        ra[1] = *(const uint4*)(Al + (size_t)gr*HID + ak8);
      } else { ra[0] = make_uint4(0,0,0,0); ra[1] = ra[0]; }
    }
    #pragma unroll
    for (int s = 0; s < 2; s++){
      int i = tid + s*256;
      int rbr = i >> 1, k8 = (i & 1)*8;
      int wrow = (rbr >> 6)*HID + n0 + (rbr & 63);
      rb[s][0] = *(const uint4*)(Wh + (size_t)wrow*HID + k8);
      rb[s][1] = *(const uint4*)(Wl + (size_t)wrow*HID + k8);
    }
  }

  for (int k0 = 0; k0 < HID; k0 += 16){
    __syncthreads();
    if (tid < 128){
      *(uint4*)&sA[0][arow][ak8] = ra[0];
      *(uint4*)&sA[1][arow][ak8] = ra[1];
    }
    #pragma unroll
    for (int s = 0; s < 2; s++){
      int i = tid + s*256;
      int rbr = i >> 1, k8 = (i & 1)*8;
      *(uint4*)&sB[0][rbr][k8] = rb[s][0];
      *(uint4*)&sB[1][rbr][k8] = rb[s][1];
    }
    __syncthreads();
    if (k0 + 16 < HID){
      int kn = k0 + 16;
      if (tid < 128){
        int gr = bm + arow;
        if (gr < rowLim){
          ra[0] = *(const uint4*)(Ah + (size_t)gr*HID + kn + ak8);
          ra[1] = *(const uint4*)(Al + (size_t)gr*HID + kn + ak8);
        } else { ra[0] = make_uint4(0,0,0,0); ra[1] = ra[0]; }
      }
      #pragma unroll
      for (int s = 0; s < 2; s++){
        int i = tid + s*256;
        int rbr = i >> 1, k8 = (i & 1)*8;
        int wrow = (rbr >> 6)*HID + n0 + (rbr & 63);
        rb[s][0] = *(const uint4*)(Wh + (size_t)wrow*HID + kn + k8);
        rb[s][1] = *(const uint4*)(Wl + (size_t)wrow*HID + kn + k8);
      }
    }
    // fragments + mma
    uint32_t afh[4], afl[4];
    {
      int r0 = warpM*16 + g8;
      afh[0] = *(const uint32_t*)&sA[0][r0  ][t4*2];
      afh[1] = *(const uint32_t*)&sA[0][r0+8][t4*2];
      afh[2] = *(const uint32_t*)&sA[0][r0  ][t4*2+8];
      afh[3] = *(const uint32_t*)&sA[0][r0+8][t4*2+8];
      afl[0] = *(const uint32_t*)&sA[1][r0  ][t4*2];
      afl[1] = *(const uint32_t*)&sA[1][r0+8][t4*2];
      afl[2] = *(const uint32_t*)&sA[1][r0  ][t4*2+8];
      afl[3] = *(const uint32_t*)&sA[1][r0+8][t4*2+8];
    }
    #pragma unroll
    for (int g = 0; g < 4; g++){
      #pragma unroll
      for (int nt = 0; nt < 4; nt++){
        int nr = g*64 + warpN*32 + nt*8 + g8;
        uint32_t bh[2], bl[2];
        bh[0] = *(const uint32_t*)&sB[0][nr][t4*2];
        bh[1] = *(const uint32_t*)&sB[0][nr][t4*2+8];
        bl[0] = *(const uint32_t*)&sB[1][nr][t4*2];
        bl[1] = *(const uint32_t*)&sB[1][nr][t4*2+8];
        mma16(acc[g][nt], afh, bh);
        mma16(acc[g][nt], afl, bh);
        mma16(acc[g][nt], afh, bl);
      }
    }
  }

  // ---- epilogue: gates -> c,h -> state + cumulative F ----
  const float* __restrict__ X = g_X[dir];
  float* __restrict__ C = g_C[dir];
  __nv_bfloat16* __restrict__ Hh = g_Hh[dir][p^1];
  __nv_bfloat16* __restrict__ Hl = g_Hl[dir][p^1];
  float* __restrict__ F = dir ? g_Fb : g_Ff;

  #pragma unroll
  for (int rr = 0; rr < 2; rr++){
    int gm = bm + warpM*16 + g8 + rr*8;
    if (gm >= rowLim) continue;
    int chain = gm >> 5, b = gm & 31;
    int t = dir ? (chain - j) : j;
    size_t xrow = (size_t)(b*NSEQ + t)*G4;
    size_t fbase;
    bool first;
    if (dir == 0){ fbase = ((size_t)(b*NSEQ + chain)*NSEQ + j)*HID; first = (j == chain); }
    else         { fbase = ((size_t)(b*NSEQ + chain)*NSEQ + t)*HID; first = (t == chain); }
    #pragma unroll
    for (int nt = 0; nt < 4; nt++){
      #pragma unroll
      for (int cc = 0; cc < 2; cc++){
        int n = n0 + warpN*32 + nt*8 + t4*2 + cc;
        int ai = rr*2 + cc;
        float gi = acc[0][nt][ai] + X[xrow + n];
        float gf = acc[1][nt][ai] + X[xrow + 512 + n];
        float gc = acc[2][nt][ai] + X[xrow + 1024 + n];
        float go = acc[3][nt][ai] + X[xrow + 1536 + n];
        size_t si = (size_t)gm*HID + n;
        float c = sigm(gf)*C[si] + sigm(gi)*tanhf(gc);
        float h = sigm(go)*tanhf(c);
        C[si] = c;
        __nv_bfloat16 hh = __float2bfloat16(h);
        Hh[si] = hh;
        Hl[si] = __float2bfloat16(h - __bfloat162float(hh));
        float prev = first ? 0.f : F[fbase + n + (dir ? (int)HID : -(int)HID)];
        F[fbase + n] = prev + h;
      }
    }
  }
}

// =======================================================================
// out GEMM: single-pass TF32 (unchanged from R3)
// =======================================================================
__global__ void out_gemm_mma(const float* __restrict__ Wout, const float* __restrict__ bout,
                             float* __restrict__ out)
{
  __shared__ uint32_t As[128][20];
  __shared__ uint32_t Bs[128][20];
  __shared__ int offF[128], offB[128], cnt[128];
  int tid = threadIdx.x, lane = tid & 31, wid = tid >> 5;
  int warpM = wid >> 2, warpN = wid & 3;
  int g = lane >> 2, t = lane & 3;
  int bm = blockIdx.y*128, bn = blockIdx.x*128;

  if (tid < 128){
    int gm = bm + tid;
    if (gm < MROWS){
      int b = gm / NPAIR, p = gm % NPAIR;
      offF[tid] = (b*NSEQ*NSEQ + g_psF[p])*HID;
      offB[tid] = (b*NSEQ*NSEQ + g_psB[p])*HID;
      cnt[tid]  = g_pcnt[p];
    } else { offF[tid] = 0; offB[tid] = 0; cnt[tid] = 0; }
  }
  __syncthreads();

  float acc[4][4][4] = {};
  for (int k0 = 0; k0 < 2*HID; k0 += 16){
    float4 av[2], bv[2];
    #pragma unroll
    for (int i = 0; i < 2; i++){
      int idx = tid + i*256;
      int m = idx >> 2, kg = (idx & 3) * 4;
      int k = k0 + kg;
      const float* src = (k < HID) ? (g_Ff + offF[m] + k) : (g_Fb + offB[m] + k - HID);
      av[i] = *(const float4*)src;
      int nn = idx >> 2;
      bv[i] = *(const float4*)(Wout + (size_t)(bn + nn)*(2*HID) + k0 + kg);
    }
    __syncthreads();
    #pragma unroll
    for (int i = 0; i < 2; i++){
      int idx = tid + i*256;
      int m = idx >> 2, kg = (idx & 3) * 4;
      As[m][kg]=f2tf(av[i].x); As[m][kg+1]=f2tf(av[i].y);
      As[m][kg+2]=f2tf(av[i].z); As[m][kg+3]=f2tf(av[i].w);
      Bs[m][kg]=f2tf(bv[i].x); Bs[m][kg+1]=f2tf(bv[i].y);
      Bs[m][kg+2]=f2tf(bv[i].z); Bs[m][kg+3]=f2tf(bv[i].w);
    }
    __syncthreads();
    #pragma unroll
    for (int ks = 0; ks < 16; ks += 8){
      uint32_t a[4][4], b[4][2];
      #pragma unroll
      for (int mt = 0; mt < 4; mt++){
        int m = warpM*64 + mt*16 + g;
        int k = ks + t;
        a[mt][0]=As[m][k];   a[mt][1]=As[m+8][k];
        a[mt][2]=As[m][k+4]; a[mt][3]=As[m+8][k+4];
      }
      #pragma unroll
      for (int nt = 0; nt < 4; nt++){
        int n = warpN*32 + nt*8 + g;
        b[nt][0]=Bs[n][ks+t]; b[nt][1]=Bs[n][ks+t+4];
      }
      #pragma unroll
      for (int mt = 0; mt < 4; mt++)
        #pragma unroll
        for (int nt = 0; nt < 4; nt++)
          mma8(acc[mt][nt], a[mt], b[nt]);
    }
    __syncthreads();
  }
  #pragma unroll
  for (int mt = 0; mt < 4; mt++){
    int r0 = warpM*64 + mt*16 + g;
    int gm0 = bm + r0;
    float c0 = (float)cnt[r0], c1 = (float)cnt[r0+8];
    #pragma unroll
    for (int nt = 0; nt < 4; nt++){
      int gn = bn + warpN*32 + nt*8 + 2*t;
      float bb0 = bout[gn], bb1 = bout[gn+1];
      if (gm0 < MROWS){
        out[(size_t)gm0*NOUT + gn]     = acc[mt][nt][0] + c0*bb0;
        out[(size_t)gm0*NOUT + gn + 1] = acc[mt][nt][1] + c0*bb1;
      }
      if (gm0 + 8 < MROWS){
        out[(size_t)(gm0+8)*NOUT + gn]     = acc[mt][nt][2] + c1*bb0;
        out[(size_t)(gm0+8)*NOUT + gn + 1] = acc[mt][nt][3] + c1*bb1;
      }
    }
  }
}

// ---------------- L2 normalize groups of 256 ----------------
__global__ void normalize_kernel(float* __restrict__ out)
{
  int w = blockIdx.x*8 + (threadIdx.x >> 5);
  int lane = threadIdx.x & 31;
  size_t base = (size_t)w*SEM;
  float v[8]; float ss = 0.f;
  #pragma unroll
  for (int i = 0; i < 8; i++){ v[i] = out[base + lane + 32*i]; ss += v[i]*v[i]; }
  #pragma unroll
  for (int o = 16; o; o >>= 1) ss += __shfl_xor_sync(0xffffffffu, ss, o);
  float sc = 1.f / fmaxf(sqrtf(ss), 1e-12f);
  #pragma unroll
  for (int i = 0; i < 8; i++) out[base + lane + 32*i] = v[i]*sc;
}

// ---------------- launcher ----------------
extern "C" void kernel_launch(void* const* d_in, const int* in_sizes, int n_in,
                              void* d_out, int out_size)
{
  const int*   captions = (const int*)  d_in[1];
  const int*   lengths  = (const int*)  d_in[2];
  const float* emb      = (const float*)d_in[3];
  const float* w_ih_f   = (const float*)d_in[4];
  const float* w_hh_f   = (const float*)d_in[5];
  const float* b_ih_f   = (const float*)d_in[6];
  const float* b_hh_f   = (const float*)d_in[7];
  const float* w_ih_b   = (const float*)d_in[8];
  const float* w_hh_b   = (const float*)d_in[9];
  const float* b_ih_b   = (const float*)d_in[10];
  const float* b_hh_b   = (const float*)d_in[11];
  const float* w_out    = (const float*)d_in[12];
  const float* b_out    = (const float*)d_in[13];
  float* out = (float*)d_out;

  float *wv, *Xf, *Xb;
  cudaGetSymbolAddress((void**)&wv, g_wv);
  cudaGetSymbolAddress((void**)&Xf, g_X);
  Xb = Xf + BSZ*NSEQ*G4;

  zero_state_kernel<<<(4*SB + 255)/256, 256>>>();
  setup_pairs_kernel<<<1, 256>>>();
  embed_kernel<<<BSZ*NSEQ, 256>>>(captions, lengths, emb);
  wsplit_kernel<<<(G4*HID + 255)/256, 256>>>(w_hh_f, w_hh_b);

  // input projections: X = wv @ W_ih^T + (b_ih + b_hh)   (3xTF32)
  gemm3x_bias<<<dim3(G4/128, (BSZ*NSEQ + 63)/64), 256>>>(
      wv, w_ih_f, b_ih_f, b_hh_f, Xf, BSZ*NSEQ, G4, DIM);
  gemm3x_bias<<<dim3(G4/128, (BSZ*NSEQ + 63)/64), 256>>>(
      wv, w_ih_b, b_ih_b, b_hh_b, Xb, BSZ*NSEQ, G4, DIM);

  // 20 fused steps (3xBF16 recurrent GEMM + gates + F cumsum)
  for (int j = 0; j < NSEQ; j++)
    lstm_fused<<<dim3(HID/64, 10, 2), 256>>>(j);

  // final projection (single-pass TF32) + per-group normalize
  out_gemm_mma<<<dim3(NOUT/128, (MROWS + 127)/128), 256>>>(w_out, b_out, out);
  normalize_kernel<<<(MROWS*30)/8, 256>>>(out);
}

// round 5
// speedup vs baseline: 3.3587x; 1.0069x over previous
#include <cuda_runtime.h>
#include <cuda_bf16.h>
#include <stdint.h>

#define BSZ 32
#define NSEQ 20
#define DIM 512
#define HID 512
#define G4 2048          // 4*HID
#define NOUT 7680        // NT*SEM
#define SEM 256
#define NPAIR 190
#define MROWS (BSZ*NPAIR)   // 6080
#define SB (NSEQ*BSZ*HID)   // 640*512 per plane

// ---------------- device scratch ----------------
__device__ float g_wv[BSZ*NSEQ*DIM];
__device__ float g_X[2][BSZ*NSEQ*G4];          // input projections (f, b)
__device__ __nv_bfloat16 g_Hh[2][2][SB];       // [dir][parity] hidden hi
__device__ __nv_bfloat16 g_Hl[2][2][SB];       // [dir][parity] hidden lo
__device__ float g_C[2][SB];                   // cell state
__device__ __nv_bfloat16 g_Wh[2][G4*HID];      // W_hh hi (f, b)
__device__ __nv_bfloat16 g_Wl[2][G4*HID];      // W_hh lo
__device__ float g_Ff[BSZ*NSEQ*NSEQ*HID];      // fp32 cumulative sums (for recurrence)
__device__ float g_Fb[BSZ*NSEQ*NSEQ*HID];
__device__ float g_FfR[BSZ*NSEQ*NSEQ*HID];     // tf32-rounded copies (for out GEMM)
__device__ float g_FbR[BSZ*NSEQ*NSEQ*HID];
__device__ float g_WoutR[NOUT*2*HID];          // tf32-rounded w_out
__device__ int   g_psF[NPAIR];
__device__ int   g_psB[NPAIR];
__device__ int   g_pcnt[NPAIR];

__device__ __forceinline__ float sigm(float x){ return 1.f/(1.f+__expf(-x)); }

__device__ __forceinline__ uint32_t f2tf(float x){
  uint32_t r; asm("cvt.rna.tf32.f32 %0, %1;" : "=r"(r) : "f"(x)); return r;
}
__device__ __forceinline__ void mma8(float c[4], const uint32_t a[4], const uint32_t b[2]){
  asm volatile("mma.sync.aligned.m16n8k8.row.col.f32.tf32.tf32.f32 "
      "{%0,%1,%2,%3}, {%4,%5,%6,%7}, {%8,%9}, {%0,%1,%2,%3};\n"
      : "+f"(c[0]), "+f"(c[1]), "+f"(c[2]), "+f"(c[3])
      : "r"(a[0]), "r"(a[1]), "r"(a[2]), "r"(a[3]), "r"(b[0]), "r"(b[1]));
}
__device__ __forceinline__ void mma16(float c[4], const uint32_t a[4], const uint32_t b[2]){
  asm volatile("mma.sync.aligned.m16n8k16.row.col.f32.bf16.bf16.f32 "
      "{%0,%1,%2,%3}, {%4,%5,%6,%7}, {%8,%9}, {%0,%1,%2,%3};\n"
      : "+f"(c[0]), "+f"(c[1]), "+f"(c[2]), "+f"(c[3])
      : "r"(a[0]), "r"(a[1]), "r"(a[2]), "r"(a[3]), "r"(b[0]), "r"(b[1]));
}

// ---------------- small setup kernels ----------------
__global__ void zero_state_kernel(){
  int i = blockIdx.x*blockDim.x + threadIdx.x;
  if (i < 4*SB){
    (&g_Hh[0][0][0])[i] = __float2bfloat16(0.f);
    (&g_Hl[0][0][0])[i] = __float2bfloat16(0.f);
  }
  if (i < 2*SB) (&g_C[0][0])[i] = 0.f;
}

__global__ void wsplit_kernel(const float* __restrict__ wf, const float* __restrict__ wb){
  int i = blockIdx.x*blockDim.x + threadIdx.x;
  if (i >= G4*HID) return;
  float w = wf[i];
  __nv_bfloat16 h = __float2bfloat16(w);
  g_Wh[0][i] = h;
  g_Wl[0][i] = __float2bfloat16(w - __bfloat162float(h));
  w = wb[i];
  h = __float2bfloat16(w);
  g_Wh[1][i] = h;
  g_Wl[1][i] = __float2bfloat16(w - __bfloat162float(h));
}

__global__ void roundW_kernel(const float* __restrict__ w){
  int i = blockIdx.x*blockDim.x + threadIdx.x;
  if (i < NOUT*2*HID) g_WoutR[i] = __uint_as_float(f2tf(w[i]));
}

__global__ void setup_pairs_kernel(){
  int p = threadIdx.x;
  if (p >= NPAIR) return;
  int cum = 0, k = 1, s = 0;
  for (int kk = 1; kk < NSEQ; kk++){
    int c = NSEQ - kk;
    if (p < cum + c){ k = kk; s = p - cum; break; }
    cum += c;
  }
  int e = s + k;
  g_psF[p] = s*NSEQ + e;
  g_psB[p] = e*NSEQ + s;
  g_pcnt[p] = k + 1;
}

__global__ void embed_kernel(const int* __restrict__ cap, const int* __restrict__ len,
                             const float* __restrict__ emb){
  int bt = blockIdx.x; int b = bt/NSEQ, t = bt%NSEQ;
  int tok = cap[bt];
  float m = (t < len[b]) ? 1.f : 0.f;
  const float* src = emb + (size_t)tok*DIM;
  for (int n = threadIdx.x; n < DIM; n += blockDim.x)
    g_wv[bt*DIM + n] = m * src[n];
}

// =======================================================================
// 3xTF32 GEMM (input projections): C = A(MxK) @ B(NxK)^T + b1 + b2
// =======================================================================
struct S3x {
  uint32_t Ah[64][20]; uint32_t Al[64][20];
  uint32_t Bh[128][20]; uint32_t Bl[128][20];
};

__global__ void gemm3x_bias(const float* __restrict__ A, const float* __restrict__ B,
                            const float* __restrict__ b1, const float* __restrict__ b2,
                            float* __restrict__ C, int M, int N, int K)
{
  __shared__ S3x s;
  int tid = threadIdx.x;
  int lane = tid & 31, wid = tid >> 5;
  int warpM = wid >> 2, warpN = wid & 3;
  int g = lane >> 2, t = lane & 3;
  int bm = blockIdx.y*64, bn = blockIdx.x*128;
  if (bm >= M) return;
  float acc[2][4][4] = {};

  for (int k0 = 0; k0 < K; k0 += 16){
    int ar = tid >> 2, ak = (tid & 3) * 4;
    int gm = bm + ar;
    float4 av = make_float4(0.f,0.f,0.f,0.f);
    if (gm < M) av = *(const float4*)(A + (size_t)gm*K + k0 + ak);
    float4 bv[2];
    #pragma unroll
    for (int i = 0; i < 2; i++){
      int idx = tid + i*256;
      int br = idx >> 2, bk = (idx & 3) * 4;
      bv[i] = *(const float4*)(B + (size_t)(bn + br)*K + k0 + bk);
    }
    __syncthreads();
    {
      uint32_t h0=f2tf(av.x), h1=f2tf(av.y), h2=f2tf(av.z), h3=f2tf(av.w);
      s.Ah[ar][ak]=h0; s.Ah[ar][ak+1]=h1; s.Ah[ar][ak+2]=h2; s.Ah[ar][ak+3]=h3;
      s.Al[ar][ak]  =f2tf(av.x-__uint_as_float(h0));
      s.Al[ar][ak+1]=f2tf(av.y-__uint_as_float(h1));
      s.Al[ar][ak+2]=f2tf(av.z-__uint_as_float(h2));
      s.Al[ar][ak+3]=f2tf(av.w-__uint_as_float(h3));
    }
    #pragma unroll
    for (int i = 0; i < 2; i++){
      int idx = tid + i*256;
      int br = idx >> 2, bk = (idx & 3) * 4;
      uint32_t h0=f2tf(bv[i].x), h1=f2tf(bv[i].y), h2=f2tf(bv[i].z), h3=f2tf(bv[i].w);
      s.Bh[br][bk]=h0; s.Bh[br][bk+1]=h1; s.Bh[br][bk+2]=h2; s.Bh[br][bk+3]=h3;
      s.Bl[br][bk]  =f2tf(bv[i].x-__uint_as_float(h0));
      s.Bl[br][bk+1]=f2tf(bv[i].y-__uint_as_float(h1));
      s.Bl[br][bk+2]=f2tf(bv[i].z-__uint_as_float(h2));
      s.Bl[br][bk+3]=f2tf(bv[i].w-__uint_as_float(h3));
    }
    __syncthreads();
    #pragma unroll
    for (int ks = 0; ks < 16; ks += 8){
      uint32_t ah[2][4], al[2][4], bh[4][2], bl[4][2];
      #pragma unroll
      for (int mt = 0; mt < 2; mt++){
        int m = warpM*32 + mt*16 + g;
        int k = ks + t;
        ah[mt][0]=s.Ah[m][k];   ah[mt][1]=s.Ah[m+8][k];
        ah[mt][2]=s.Ah[m][k+4]; ah[mt][3]=s.Ah[m+8][k+4];
        al[mt][0]=s.Al[m][k];   al[mt][1]=s.Al[m+8][k];
        al[mt][2]=s.Al[m][k+4]; al[mt][3]=s.Al[m+8][k+4];
      }
      #pragma unroll
      for (int nt = 0; nt < 4; nt++){
        int n = warpN*32 + nt*8 + g;
        bh[nt][0]=s.Bh[n][ks+t]; bh[nt][1]=s.Bh[n][ks+t+4];
        bl[nt][0]=s.Bl[n][ks+t]; bl[nt][1]=s.Bl[n][ks+t+4];
      }
      #pragma unroll
      for (int mt = 0; mt < 2; mt++)
        #pragma unroll
        for (int nt = 0; nt < 4; nt++){
          mma8(acc[mt][nt], ah[mt], bh[nt]);
          mma8(acc[mt][nt], al[mt], bh[nt]);
          mma8(acc[mt][nt], ah[mt], bl[nt]);
        }
    }
    __syncthreads();
  }
  #pragma unroll
  for (int mt = 0; mt < 2; mt++){
    int r0 = bm + warpM*32 + mt*16 + g;
    #pragma unroll
    for (int nt = 0; nt < 4; nt++){
      int gn = bn + warpN*32 + nt*8 + 2*t;
      float e0 = b1[gn] + b2[gn], e1 = b1[gn+1] + b2[gn+1];
      if (r0 < M){
        C[(size_t)r0*N + gn]     = acc[mt][nt][0] + e0;
        C[(size_t)r0*N + gn + 1] = acc[mt][nt][1] + e1;
      }
      if (r0 + 8 < M){
        C[(size_t)(r0+8)*N + gn]     = acc[mt][nt][2] + e0;
        C[(size_t)(r0+8)*N + gn + 1] = acc[mt][nt][3] + e1;
      }
    }
  }
}

// =======================================================================
// Fused LSTM step: 3xBF16 recurrent GEMM + gates + state + F cumsum
// =======================================================================
__global__ void lstm_fused(int j)
{
  const int dir = blockIdx.z;
  const int n0 = blockIdx.x * 64;
  const int p = j & 1;
  int bm, rowLim;
  if (dir == 0){
    rowLim = (j+1)*BSZ;
    bm = blockIdx.y * 64;
    if (bm >= rowLim) return;
  } else {
    rowLim = NSEQ*BSZ;
    bm = j*BSZ + blockIdx.y*64;
    if (bm >= rowLim) return;
  }
  const __nv_bfloat16* __restrict__ Ah = g_Hh[dir][p];
  const __nv_bfloat16* __restrict__ Al = g_Hl[dir][p];
  const __nv_bfloat16* __restrict__ Wh = g_Wh[dir];
  const __nv_bfloat16* __restrict__ Wl = g_Wl[dir];

  __shared__ __align__(16) uint16_t sA[2][64][24];
  __shared__ __align__(16) uint16_t sB[2][256][24];

  const int tid = threadIdx.x, lane = tid & 31, wid = tid >> 5;
  const int warpM = wid & 3, warpN = wid >> 2;
  const int g8 = lane >> 2, t4 = lane & 3;

  float acc[4][4][4] = {};

  uint4 ra[2]; uint4 rb[2][2];
  const int arow = tid >> 1, ak8 = (tid & 1)*8;

  {
    if (tid < 128){
      int gr = bm + arow;
      if (gr < rowLim){
        ra[0] = *(const uint4*)(Ah + (size_t)gr*HID + ak8);
        ra[1] = *(const uint4*)(Al + (size_t)gr*HID + ak8);
      } else { ra[0] = make_uint4(0,0,0,0); ra[1] = ra[0]; }
    }
    #pragma unroll
    for (int s = 0; s < 2; s++){
      int i = tid + s*256;
      int rbr = i >> 1, k8 = (i & 1)*8;
      int wrow = (rbr >> 6)*HID + n0 + (rbr & 63);
      rb[s][0] = *(const uint4*)(Wh + (size_t)wrow*HID + k8);
      rb[s][1] = *(const uint4*)(Wl + (size_t)wrow*HID + k8);
    }
  }

  for (int k0 = 0; k0 < HID; k0 += 16){
    __syncthreads();
    if (tid < 128){
      *(uint4*)&sA[0][arow][ak8] = ra[0];
      *(uint4*)&sA[1][arow][ak8] = ra[1];
    }
    #pragma unroll
    for (int s = 0; s < 2; s++){
      int i = tid + s*256;
      int rbr = i >> 1, k8 = (i & 1)*8;
      *(uint4*)&sB[0][rbr][k8] = rb[s][0];
      *(uint4*)&sB[1][rbr][k8] = rb[s][1];
    }
    __syncthreads();
    if (k0 + 16 < HID){
      int kn = k0 + 16;
      if (tid < 128){
        int gr = bm + arow;
        if (gr < rowLim){
          ra[0] = *(const uint4*)(Ah + (size_t)gr*HID + kn + ak8);
          ra[1] = *(const uint4*)(Al + (size_t)gr*HID + kn + ak8);
        } else { ra[0] = make_uint4(0,0,0,0); ra[1] = ra[0]; }
      }
      #pragma unroll
      for (int s = 0; s < 2; s++){
        int i = tid + s*256;
        int rbr = i >> 1, k8 = (i & 1)*8;
        int wrow = (rbr >> 6)*HID + n0 + (rbr & 63);
        rb[s][0] = *(const uint4*)(Wh + (size_t)wrow*HID + kn + k8);
        rb[s][1] = *(const uint4*)(Wl + (size_t)wrow*HID + kn + k8);
      }
    }
    uint32_t afh[4], afl[4];
    {
      int r0 = warpM*16 + g8;
      afh[0] = *(const uint32_t*)&sA[0][r0  ][t4*2];
      afh[1] = *(const uint32_t*)&sA[0][r0+8][t4*2];
      afh[2] = *(const uint32_t*)&sA[0][r0  ][t4*2+8];
      afh[3] = *(const uint32_t*)&sA[0][r0+8][t4*2+8];
      afl[0] = *(const uint32_t*)&sA[1][r0  ][t4*2];
      afl[1] = *(const uint32_t*)&sA[1][r0+8][t4*2];
      afl[2] = *(const uint32_t*)&sA[1][r0  ][t4*2+8];
      afl[3] = *(const uint32_t*)&sA[1][r0+8][t4*2+8];
    }
    #pragma unroll
    for (int g = 0; g < 4; g++){
      #pragma unroll
      for (int nt = 0; nt < 4; nt++){
        int nr = g*64 + warpN*32 + nt*8 + g8;
        uint32_t bh[2], bl[2];
        bh[0] = *(const uint32_t*)&sB[0][nr][t4*2];
        bh[1] = *(const uint32_t*)&sB[0][nr][t4*2+8];
        bl[0] = *(const uint32_t*)&sB[1][nr][t4*2];
        bl[1] = *(const uint32_t*)&sB[1][nr][t4*2+8];
        mma16(acc[g][nt], afh, bh);
        mma16(acc[g][nt], afl, bh);
        mma16(acc[g][nt], afh, bl);
      }
    }
  }

  // ---- epilogue ----
  const float* __restrict__ X = g_X[dir];
  float* __restrict__ C = g_C[dir];
  __nv_bfloat16* __restrict__ Hh = g_Hh[dir][p^1];
  __nv_bfloat16* __restrict__ Hl = g_Hl[dir][p^1];
  float* __restrict__ F  = dir ? g_Fb  : g_Ff;
  float* __restrict__ FR = dir ? g_FbR : g_FfR;

  #pragma unroll
  for (int rr = 0; rr < 2; rr++){
    int gm = bm + warpM*16 + g8 + rr*8;
    if (gm >= rowLim) continue;
    int chain = gm >> 5, b = gm & 31;
    int t = dir ? (chain - j) : j;
    size_t xrow = (size_t)(b*NSEQ + t)*G4;
    size_t fbase;
    bool first;
    if (dir == 0){ fbase = ((size_t)(b*NSEQ + chain)*NSEQ + j)*HID; first = (j == chain); }
    else         { fbase = ((size_t)(b*NSEQ + chain)*NSEQ + t)*HID; first = (t == chain); }
    #pragma unroll
    for (int nt = 0; nt < 4; nt++){
      #pragma unroll
      for (int cc = 0; cc < 2; cc++){
        int n = n0 + warpN*32 + nt*8 + t4*2 + cc;
        int ai = rr*2 + cc;
        float gi = acc[0][nt][ai] + X[xrow + n];
        float gf = acc[1][nt][ai] + X[xrow + 512 + n];
        float gc = acc[2][nt][ai] + X[xrow + 1024 + n];
        float go = acc[3][nt][ai] + X[xrow + 1536 + n];
        size_t si = (size_t)gm*HID + n;
        float c = sigm(gf)*C[si] + sigm(gi)*tanhf(gc);
        float h = sigm(go)*tanhf(c);
        C[si] = c;
        __nv_bfloat16 hh = __float2bfloat16(h);
        Hh[si] = hh;
        Hl[si] = __float2bfloat16(h - __bfloat162float(hh));
        float prev = first ? 0.f : F[fbase + n + (dir ? (int)HID : -(int)HID)];
        float v = prev + h;
        F[fbase + n]  = v;
        FR[fbase + n] = __uint_as_float(f2tf(v));
      }
    }
  }
}

// =======================================================================
// out GEMM: single-pass TF32, register-prefetch double buffered, no cvt.
// M=6080 (gathered), N=7680, K=1024.  BM=BN=128, BK=16, 256 thr.
// =======================================================================
__global__ __launch_bounds__(256) void out_gemm_mma(const float* __restrict__ bout,
                                                    float* __restrict__ out)
{
  __shared__ __align__(16) float As[128][20];
  __shared__ __align__(16) float Bs[128][20];
  __shared__ int offF[128], offB[128], cnt[128];
  const int tid = threadIdx.x, lane = tid & 31, wid = tid >> 5;
  const int warpM = wid >> 2, warpN = wid & 3;
  const int g = lane >> 2, t = lane & 3;
  const int bm = blockIdx.y*128, bn = blockIdx.x*128;

  if (tid < 128){
    int gm = bm + tid;
    if (gm < MROWS){
      int b = gm / NPAIR, p = gm % NPAIR;
      offF[tid] = (b*NSEQ*NSEQ + g_psF[p])*HID;
      offB[tid] = (b*NSEQ*NSEQ + g_psB[p])*HID;
      cnt[tid]  = g_pcnt[p];
    } else { offF[tid] = 0; offB[tid] = 0; cnt[tid] = 0; }
  }
  __syncthreads();

  const int m = tid >> 2, kg = (tid & 3) * 4;   // loader coords (A row / B row = m)
  float4 av[2], bv[2];
  // prefetch k0 = 0
  #pragma unroll
  for (int i = 0; i < 2; i++){
    int mm = m + i*64;
    const float* srcA = (kg < HID) ? (g_FfR + offF[mm] + kg) : (g_FbR + offB[mm] + kg - HID);
    av[i] = *(const float4*)srcA;
    bv[i] = *(const float4*)(g_WoutR + (size_t)(bn + mm)*(2*HID) + kg);
  }

  float acc[4][4][4] = {};
  for (int k0 = 0; k0 < 2*HID; k0 += 16){
    __syncthreads();
    #pragma unroll
    for (int i = 0; i < 2; i++){
      *(float4*)&As[m + i*64][kg] = av[i];
      *(float4*)&Bs[m + i*64][kg] = bv[i];
    }
    __syncthreads();
    if (k0 + 16 < 2*HID){
      int k = k0 + 16 + kg;
      #pragma unroll
      for (int i = 0; i < 2; i++){
        int mm = m + i*64;
        const float* srcA = (k < HID) ? (g_FfR + offF[mm] + k) : (g_FbR + offB[mm] + k - HID);
        av[i] = *(const float4*)srcA;
        bv[i] = *(const float4*)(g_WoutR + (size_t)(bn + mm)*(2*HID) + k0 + 16 + kg);
      }
    }
    #pragma unroll
    for (int ks = 0; ks < 16; ks += 8){
      uint32_t a[4][4], b[4][2];
      #pragma unroll
      for (int mt = 0; mt < 4; mt++){
        int mr = warpM*64 + mt*16 + g;
        int k = ks + t;
        a[mt][0]=*(const uint32_t*)&As[mr][k];     a[mt][1]=*(const uint32_t*)&As[mr+8][k];
        a[mt][2]=*(const uint32_t*)&As[mr][k+4];   a[mt][3]=*(const uint32_t*)&As[mr+8][k+4];
      }
      #pragma unroll
      for (int nt = 0; nt < 4; nt++){
        int nr = warpN*32 + nt*8 + g;
        b[nt][0]=*(const uint32_t*)&Bs[nr][ks+t];  b[nt][1]=*(const uint32_t*)&Bs[nr][ks+t+4];
      }
      #pragma unroll
      for (int mt = 0; mt < 4; mt++)
        #pragma unroll
        for (int nt = 0; nt < 4; nt++)
          mma8(acc[mt][nt], a[mt], b[nt]);
    }
  }
  // epilogue: + cnt * bias
  #pragma unroll
  for (int mt = 0; mt < 4; mt++){
    int r0 = warpM*64 + mt*16 + g;
    int gm0 = bm + r0;
    float c0 = (float)cnt[r0], c1 = (float)cnt[r0+8];
    #pragma unroll
    for (int nt = 0; nt < 4; nt++){
      int gn = bn + warpN*32 + nt*8 + 2*t;
      float bb0 = bout[gn], bb1 = bout[gn+1];
      if (gm0 < MROWS){
        out[(size_t)gm0*NOUT + gn]     = acc[mt][nt][0] + c0*bb0;
        out[(size_t)gm0*NOUT + gn + 1] = acc[mt][nt][1] + c0*bb1;
      }
      if (gm0 + 8 < MROWS){
        out[(size_t)(gm0+8)*NOUT + gn]     = acc[mt][nt][2] + c1*bb0;
        out[(size_t)(gm0+8)*NOUT + gn + 1] = acc[mt][nt][3] + c1*bb1;
      }
    }
  }
}

// ---------------- L2 normalize groups of 256 ----------------
__global__ void normalize_kernel(float* __restrict__ out)
{
  int w = blockIdx.x*8 + (threadIdx.x >> 5);
  int lane = threadIdx.x & 31;
  size_t base = (size_t)w*SEM;
  float v[8]; float ss = 0.f;
  #pragma unroll
  for (int i = 0; i < 8; i++){ v[i] = out[base + lane + 32*i]; ss += v[i]*v[i]; }
  #pragma unroll
  for (int o = 16; o; o >>= 1) ss += __shfl_xor_sync(0xffffffffu, ss, o);
  float sc = 1.f / fmaxf(sqrtf(ss), 1e-12f);
  #pragma unroll
  for (int i = 0; i < 8; i++) out[base + lane + 32*i] = v[i]*sc;
}

// ---------------- launcher ----------------
extern "C" void kernel_launch(void* const* d_in, const int* in_sizes, int n_in,
                              void* d_out, int out_size)
{
  const int*   captions = (const int*)  d_in[1];
  const int*   lengths  = (const int*)  d_in[2];
  const float* emb      = (const float*)d_in[3];
  const float* w_ih_f   = (const float*)d_in[4];
  const float* w_hh_f   = (const float*)d_in[5];
  const float* b_ih_f   = (const float*)d_in[6];
  const float* b_hh_f   = (const float*)d_in[7];
  const float* w_ih_b   = (const float*)d_in[8];
  const float* w_hh_b   = (const float*)d_in[9];
  const float* b_ih_b   = (const float*)d_in[10];
  const float* b_hh_b   = (const float*)d_in[11];
  const float* w_out    = (const float*)d_in[12];
  const float* b_out    = (const float*)d_in[13];
  float* out = (float*)d_out;

  float *wv, *Xf, *Xb;
  cudaGetSymbolAddress((void**)&wv, g_wv);
  cudaGetSymbolAddress((void**)&Xf, g_X);
  Xb = Xf + BSZ*NSEQ*G4;

  zero_state_kernel<<<(4*SB + 255)/256, 256>>>();
  setup_pairs_kernel<<<1, 256>>>();
  embed_kernel<<<BSZ*NSEQ, 256>>>(captions, lengths, emb);
  wsplit_kernel<<<(G4*HID + 255)/256, 256>>>(w_hh_f, w_hh_b);
  roundW_kernel<<<(NOUT*2*HID + 255)/256, 256>>>(w_out);

  gemm3x_bias<<<dim3(G4/128, (BSZ*NSEQ + 63)/64), 256>>>(
      wv, w_ih_f, b_ih_f, b_hh_f, Xf, BSZ*NSEQ, G4, DIM);
  gemm3x_bias<<<dim3(G4/128, (BSZ*NSEQ + 63)/64), 256>>>(
      wv, w_ih_b, b_ih_b, b_hh_b, Xb, BSZ*NSEQ, G4, DIM);

  for (int j = 0; j < NSEQ; j++)
    lstm_fused<<<dim3(HID/64, 10, 2), 256>>>(j);

  out_gemm_mma<<<dim3(NOUT/128, (MROWS + 127)/128), 256>>>(b_out, out);
  normalize_kernel<<<(MROWS*30)/8, 256>>>(out);
}

// round 7
// speedup vs baseline: 3.8527x; 1.1471x over previous
#include <cuda_runtime.h>
#include <cuda_bf16.h>
#include <cuda_fp16.h>
#include <stdint.h>

#define BSZ 32
#define NSEQ 20
#define DIM 512
#define HID 512
#define G4 2048          // 4*HID
#define NOUT 7680        // NT*SEM
#define SEM 256
#define NPAIR 190
#define MROWS (BSZ*NPAIR)   // 6080
#define SB (NSEQ*BSZ*HID)   // 640*512 per plane
#define FSZ (BSZ*NSEQ*NSEQ*HID)

// ---------------- device scratch ----------------
__device__ float g_wv[BSZ*NSEQ*DIM];
__device__ float g_X[2][BSZ*NSEQ*G4];          // input projections (f, b)
__device__ __nv_bfloat16 g_Hh[2][2][SB];       // [dir][parity] hidden hi
__device__ __nv_bfloat16 g_Hl[2][2][SB];       // [dir][parity] hidden lo
__device__ float g_C[2][SB];                   // cell state
__device__ __nv_bfloat16 g_Wh[2][G4*HID];      // W_hh hi (f, b)
__device__ __nv_bfloat16 g_Wl[2][G4*HID];      // W_hh lo
__device__ float g_Ff[FSZ];                    // fp32 cumulative sums (recurrence use)
__device__ float g_Fb[FSZ];
__device__ __half g_FF16[FSZ];                 // fp16 cumsum planes (out GEMM)
__device__ __half g_FB16[FSZ];
__device__ __half g_WO16[NOUT*2*HID];          // fp16 w_out
__device__ int   g_psF[NPAIR];
__device__ int   g_psB[NPAIR];
__device__ int   g_pcnt[NPAIR];

__device__ __forceinline__ float sigm(float x){ return 1.f/(1.f+__expf(-x)); }

__device__ __forceinline__ uint32_t f2tf(float x){
  uint32_t r; asm("cvt.rna.tf32.f32 %0, %1;" : "=r"(r) : "f"(x)); return r;
}
__device__ __forceinline__ void mma8(float c[4], const uint32_t a[4], const uint32_t b[2]){
  asm volatile("mma.sync.aligned.m16n8k8.row.col.f32.tf32.tf32.f32 "
      "{%0,%1,%2,%3}, {%4,%5,%6,%7}, {%8,%9}, {%0,%1,%2,%3};\n"
      : "+f"(c[0]), "+f"(c[1]), "+f"(c[2]), "+f"(c[3])
      : "r"(a[0]), "r"(a[1]), "r"(a[2]), "r"(a[3]), "r"(b[0]), "r"(b[1]));
}
__device__ __forceinline__ void mma16bf(float c[4], const uint32_t a[4], const uint32_t b[2]){
  asm volatile("mma.sync.aligned.m16n8k16.row.col.f32.bf16.bf16.f32 "
      "{%0,%1,%2,%3}, {%4,%5,%6,%7}, {%8,%9}, {%0,%1,%2,%3};\n"
      : "+f"(c[0]), "+f"(c[1]), "+f"(c[2]), "+f"(c[3])
      : "r"(a[0]), "r"(a[1]), "r"(a[2]), "r"(a[3]), "r"(b[0]), "r"(b[1]));
}
__device__ __forceinline__ void mma16h(float c[4], const uint32_t a[4], const uint32_t b[2]){
  asm volatile("mma.sync.aligned.m16n8k16.row.col.f32.f16.f16.f32 "
      "{%0,%1,%2,%3}, {%4,%5,%6,%7}, {%8,%9}, {%0,%1,%2,%3};\n"
      : "+f"(c[0]), "+f"(c[1]), "+f"(c[2]), "+f"(c[3])
      : "r"(a[0]), "r"(a[1]), "r"(a[2]), "r"(a[3]), "r"(b[0]), "r"(b[1]));
}

// ---------------- small setup kernels ----------------
__global__ void zero_state_kernel(){
  int i = blockIdx.x*blockDim.x + threadIdx.x;
  if (i < 4*SB){
    (&g_Hh[0][0][0])[i] = __float2bfloat16(0.f);
    (&g_Hl[0][0][0])[i] = __float2bfloat16(0.f);
  }
  if (i < 2*SB) (&g_C[0][0])[i] = 0.f;
}

__global__ void wsplit_kernel(const float* __restrict__ wf, const float* __restrict__ wb){
  int i = blockIdx.x*blockDim.x + threadIdx.x;
  if (i >= G4*HID) return;
  float w = wf[i];
  __nv_bfloat16 h = __float2bfloat16(w);
  g_Wh[0][i] = h;
  g_Wl[0][i] = __float2bfloat16(w - __bfloat162float(h));
  w = wb[i];
  h = __float2bfloat16(w);
  g_Wh[1][i] = h;
  g_Wl[1][i] = __float2bfloat16(w - __bfloat162float(h));
}

__global__ void wout16_kernel(const float* __restrict__ w){
  int i = blockIdx.x*blockDim.x + threadIdx.x;
  if (i < NOUT*2*HID) g_WO16[i] = __float2half(w[i]);
}

__global__ void setup_pairs_kernel(){
  int p = threadIdx.x;
  if (p >= NPAIR) return;
  int cum = 0, k = 1, s = 0;
  for (int kk = 1; kk < NSEQ; kk++){
    int c = NSEQ - kk;
    if (p < cum + c){ k = kk; s = p - cum; break; }
    cum += c;
  }
  int e = s + k;
  g_psF[p] = s*NSEQ + e;
  g_psB[p] = e*NSEQ + s;
  g_pcnt[p] = k + 1;
}

__global__ void embed_kernel(const int* __restrict__ cap, const int* __restrict__ len,
                             const float* __restrict__ emb){
  int bt = blockIdx.x; int b = bt/NSEQ, t = bt%NSEQ;
  int tok = cap[bt];
  float m = (t < len[b]) ? 1.f : 0.f;
  const float* src = emb + (size_t)tok*DIM;
  for (int n = threadIdx.x; n < DIM; n += blockDim.x)
    g_wv[bt*DIM + n] = m * src[n];
}

// =======================================================================
// 3xTF32 GEMM (input projections)
// =======================================================================
struct S3x {
  uint32_t Ah[64][20]; uint32_t Al[64][20];
  uint32_t Bh[128][20]; uint32_t Bl[128][20];
};

__global__ void gemm3x_bias(const float* __restrict__ A, const float* __restrict__ B,
                            const float* __restrict__ b1, const float* __restrict__ b2,
                            float* __restrict__ C, int M, int N, int K)
{
  __shared__ S3x s;
  int tid = threadIdx.x;
  int lane = tid & 31, wid = tid >> 5;
  int warpM = wid >> 2, warpN = wid & 3;
  int g = lane >> 2, t = lane & 3;
  int bm = blockIdx.y*64, bn = blockIdx.x*128;
  if (bm >= M) return;
  float acc[2][4][4] = {};

  for (int k0 = 0; k0 < K; k0 += 16){
    int ar = tid >> 2, ak = (tid & 3) * 4;
    int gm = bm + ar;
    float4 av = make_float4(0.f,0.f,0.f,0.f);
    if (gm < M) av = *(const float4*)(A + (size_t)gm*K + k0 + ak);
    float4 bv[2];
    #pragma unroll
    for (int i = 0; i < 2; i++){
      int idx = tid + i*256;
      int br = idx >> 2, bk = (idx & 3) * 4;
      bv[i] = *(const float4*)(B + (size_t)(bn + br)*K + k0 + bk);
    }
    __syncthreads();
    {
      uint32_t h0=f2tf(av.x), h1=f2tf(av.y), h2=f2tf(av.z), h3=f2tf(av.w);
      s.Ah[ar][ak]=h0; s.Ah[ar][ak+1]=h1; s.Ah[ar][ak+2]=h2; s.Ah[ar][ak+3]=h3;
      s.Al[ar][ak]  =f2tf(av.x-__uint_as_float(h0));
      s.Al[ar][ak+1]=f2tf(av.y-__uint_as_float(h1));
      s.Al[ar][ak+2]=f2tf(av.z-__uint_as_float(h2));
      s.Al[ar][ak+3]=f2tf(av.w-__uint_as_float(h3));
    }
    #pragma unroll
    for (int i = 0; i < 2; i++){
      int idx = tid + i*256;
      int br = idx >> 2, bk = (idx & 3) * 4;
      uint32_t h0=f2tf(bv[i].x), h1=f2tf(bv[i].y), h2=f2tf(bv[i].z), h3=f2tf(bv[i].w);
      s.Bh[br][bk]=h0; s.Bh[br][bk+1]=h1; s.Bh[br][bk+2]=h2; s.Bh[br][bk+3]=h3;
      s.Bl[br][bk]  =f2tf(bv[i].x-__uint_as_float(h0));
      s.Bl[br][bk+1]=f2tf(bv[i].y-__uint_as_float(h1));
      s.Bl[br][bk+2]=f2tf(bv[i].z-__uint_as_float(h2));
      s.Bl[br][bk+3]=f2tf(bv[i].w-__uint_as_float(h3));
    }
    __syncthreads();
    #pragma unroll
    for (int ks = 0; ks < 16; ks += 8){
      uint32_t ah[2][4], al[2][4], bh[4][2], bl[4][2];
      #pragma unroll
      for (int mt = 0; mt < 2; mt++){
        int m = warpM*32 + mt*16 + g;
        int k = ks + t;
        ah[mt][0]=s.Ah[m][k];   ah[mt][1]=s.Ah[m+8][k];
        ah[mt][2]=s.Ah[m][k+4]; ah[mt][3]=s.Ah[m+8][k+4];
        al[mt][0]=s.Al[m][k];   al[mt][1]=s.Al[m+8][k];
        al[mt][2]=s.Al[m][k+4]; al[mt][3]=s.Al[m+8][k+4];
      }
      #pragma unroll
      for (int nt = 0; nt < 4; nt++){
        int n = warpN*32 + nt*8 + g;
        bh[nt][0]=s.Bh[n][ks+t]; bh[nt][1]=s.Bh[n][ks+t+4];
        bl[nt][0]=s.Bl[n][ks+t]; bl[nt][1]=s.Bl[n][ks+t+4];
      }
      #pragma unroll
      for (int mt = 0; mt < 2; mt++)
        #pragma unroll
        for (int nt = 0; nt < 4; nt++){
          mma8(acc[mt][nt], ah[mt], bh[nt]);
          mma8(acc[mt][nt], al[mt], bh[nt]);
          mma8(acc[mt][nt], ah[mt], bl[nt]);
        }
    }
    __syncthreads();
  }
  #pragma unroll
  for (int mt = 0; mt < 2; mt++){
    int r0 = bm + warpM*32 + mt*16 + g;
    #pragma unroll
    for (int nt = 0; nt < 4; nt++){
      int gn = bn + warpN*32 + nt*8 + 2*t;
      float e0 = b1[gn] + b2[gn], e1 = b1[gn+1] + b2[gn+1];
      if (r0 < M){
        C[(size_t)r0*N + gn]     = acc[mt][nt][0] + e0;
        C[(size_t)r0*N + gn + 1] = acc[mt][nt][1] + e1;
      }
      if (r0 + 8 < M){
        C[(size_t)(r0+8)*N + gn]     = acc[mt][nt][2] + e0;
        C[(size_t)(r0+8)*N + gn + 1] = acc[mt][nt][3] + e1;
      }
    }
  }
}

// =======================================================================
// Fused LSTM step: 3xBF16 recurrent GEMM + gates + state + F cumsum
// =======================================================================
__global__ void lstm_fused(int j)
{
  const int dir = blockIdx.z;
  const int n0 = blockIdx.x * 64;
  const int p = j & 1;
  int bm, rowLim;
  if (dir == 0){
    rowLim = (j+1)*BSZ;
    bm = blockIdx.y * 64;
    if (bm >= rowLim) return;
  } else {
    rowLim = NSEQ*BSZ;
    bm = j*BSZ + blockIdx.y*64;
    if (bm >= rowLim) return;
  }
  const __nv_bfloat16* __restrict__ Ah = g_Hh[dir][p];
  const __nv_bfloat16* __restrict__ Al = g_Hl[dir][p];
  const __nv_bfloat16* __restrict__ Wh = g_Wh[dir];
  const __nv_bfloat16* __restrict__ Wl = g_Wl[dir];

  __shared__ __align__(16) uint16_t sA[2][64][24];
  __shared__ __align__(16) uint16_t sB[2][256][24];

  const int tid = threadIdx.x, lane = tid & 31, wid = tid >> 5;
  const int warpM = wid & 3, warpN = wid >> 2;
  const int g8 = lane >> 2, t4 = lane & 3;

  float acc[4][4][4] = {};

  uint4 ra[2]; uint4 rb[2][2];
  const int arow = tid >> 1, ak8 = (tid & 1)*8;

  {
    if (tid < 128){
      int gr = bm + arow;
      if (gr < rowLim){
        ra[0] = *(const uint4*)(Ah + (size_t)gr*HID + ak8);
        ra[1] = *(const uint4*)(Al + (size_t)gr*HID + ak8);
      } else { ra[0] = make_uint4(0,0,0,0); ra[1] = ra[0]; }
    }
    #pragma unroll
    for (int s = 0; s < 2; s++){
      int i = tid + s*256;
      int rbr = i >> 1, k8 = (i & 1)*8;
      int wrow = (rbr >> 6)*HID + n0 + (rbr & 63);
      rb[s][0] = *(const uint4*)(Wh + (size_t)wrow*HID + k8);
      rb[s][1] = *(const uint4*)(Wl + (size_t)wrow*HID + k8);
    }
  }

  for (int k0 = 0; k0 < HID; k0 += 16){
    __syncthreads();
    if (tid < 128){
      *(uint4*)&sA[0][arow][ak8] = ra[0];
      *(uint4*)&sA[1][arow][ak8] = ra[1];
    }
    #pragma unroll
    for (int s = 0; s < 2; s++){
      int i = tid + s*256;
      int rbr = i >> 1, k8 = (i & 1)*8;
      *(uint4*)&sB[0][rbr][k8] = rb[s][0];
      *(uint4*)&sB[1][rbr][k8] = rb[s][1];
    }
    __syncthreads();
    if (k0 + 16 < HID){
      int kn = k0 + 16;
      if (tid < 128){
        int gr = bm + arow;
        if (gr < rowLim){
          ra[0] = *(const uint4*)(Ah + (size_t)gr*HID + kn + ak8);
          ra[1] = *(const uint4*)(Al + (size_t)gr*HID + kn + ak8);
        } else { ra[0] = make_uint4(0,0,0,0); ra[1] = ra[0]; }
      }
      #pragma unroll
      for (int s = 0; s < 2; s++){
        int i = tid + s*256;
        int rbr = i >> 1, k8 = (i & 1)*8;
        int wrow = (rbr >> 6)*HID + n0 + (rbr & 63);
        rb[s][0] = *(const uint4*)(Wh + (size_t)wrow*HID + kn + k8);
        rb[s][1] = *(const uint4*)(Wl + (size_t)wrow*HID + kn + k8);
      }
    }
    uint32_t afh[4], afl[4];
    {
      int r0 = warpM*16 + g8;
      afh[0] = *(const uint32_t*)&sA[0][r0  ][t4*2];
      afh[1] = *(const uint32_t*)&sA[0][r0+8][t4*2];
      afh[2] = *(const uint32_t*)&sA[0][r0  ][t4*2+8];
      afh[3] = *(const uint32_t*)&sA[0][r0+8][t4*2+8];
      afl[0] = *(const uint32_t*)&sA[1][r0  ][t4*2];
      afl[1] = *(const uint32_t*)&sA[1][r0+8][t4*2];
      afl[2] = *(const uint32_t*)&sA[1][r0  ][t4*2+8];
      afl[3] = *(const uint32_t*)&sA[1][r0+8][t4*2+8];
    }
    #pragma unroll
    for (int g = 0; g < 4; g++){
      #pragma unroll
      for (int nt = 0; nt < 4; nt++){
        int nr = g*64 + warpN*32 + nt*8 + g8;
        uint32_t bh[2], bl[2];
        bh[0] = *(const uint32_t*)&sB[0][nr][t4*2];
        bh[1] = *(const uint32_t*)&sB[0][nr][t4*2+8];
        bl[0] = *(const uint32_t*)&sB[1][nr][t4*2];
        bl[1] = *(const uint32_t*)&sB[1][nr][t4*2+8];
        mma16bf(acc[g][nt], afh, bh);
        mma16bf(acc[g][nt], afl, bh);
        mma16bf(acc[g][nt], afh, bl);
      }
    }
  }

  // ---- epilogue ----
  const float* __restrict__ X = g_X[dir];
  float* __restrict__ C = g_C[dir];
  __nv_bfloat16* __restrict__ Hh = g_Hh[dir][p^1];
  __nv_bfloat16* __restrict__ Hl = g_Hl[dir][p^1];
  float* __restrict__ F  = dir ? g_Fb  : g_Ff;
  __half* __restrict__ F16 = dir ? g_FB16 : g_FF16;

  #pragma unroll
  for (int rr = 0; rr < 2; rr++){
    int gm = bm + warpM*16 + g8 + rr*8;
    if (gm >= rowLim) continue;
    int chain = gm >> 5, b = gm & 31;
    int t = dir ? (chain - j) : j;
    size_t xrow = (size_t)(b*NSEQ + t)*G4;
    size_t fbase;
    bool first;
    if (dir == 0){ fbase = ((size_t)(b*NSEQ + chain)*NSEQ + j)*HID; first = (j == chain); }
    else         { fbase = ((size_t)(b*NSEQ + chain)*NSEQ + t)*HID; first = (t == chain); }
    #pragma unroll
    for (int nt = 0; nt < 4; nt++){
      #pragma unroll
      for (int cc = 0; cc < 2; cc++){
        int n = n0 + warpN*32 + nt*8 + t4*2 + cc;
        int ai = rr*2 + cc;
        float gi = acc[0][nt][ai] + X[xrow + n];
        float gf = acc[1][nt][ai] + X[xrow + 512 + n];
        float gc = acc[2][nt][ai] + X[xrow + 1024 + n];
        float go = acc[3][nt][ai] + X[xrow + 1536 + n];
        size_t si = (size_t)gm*HID + n;
        float c = sigm(gf)*C[si] + sigm(gi)*tanhf(gc);
        float h = sigm(go)*tanhf(c);
        C[si] = c;
        __nv_bfloat16 hh = __float2bfloat16(h);
        Hh[si] = hh;
        Hl[si] = __float2bfloat16(h - __bfloat162float(hh));
        float prev = first ? 0.f : F[fbase + n + (dir ? (int)HID : -(int)HID)];
        float v = prev + h;
        F[fbase + n]   = v;
        F16[fbase + n] = __float2half(v);
      }
    }
  }
}

// =======================================================================
// out GEMM: single-pass FP16 m16n8k16.  M=6080 (gathered), N=7680, K=1024
// BM=BN=128, BK=32, 256 threads = 8 warps (2 M x 4 N), warp tile 64x32.
// smem row stride 40 halves (80B): conflict-free frag loads, 16B-aligned stages.
// =======================================================================
__global__ __launch_bounds__(256) void out_gemm_fp16(const float* __restrict__ bout,
                                                     float* __restrict__ out)
{
  __shared__ __align__(16) __half sA[128][40];
  __shared__ __align__(16) __half sB[128][40];
  __shared__ int offF[128], offB[128], cnt[128];
  const int tid = threadIdx.x, lane = tid & 31, wid = tid >> 5;
  const int warpM = wid >> 2, warpN = wid & 3;
  const int g = lane >> 2, t4 = lane & 3;
  const int bm = blockIdx.y*128, bn = blockIdx.x*128;

  if (tid < 128){
    int gm = bm + tid;
    if (gm < MROWS){
      int b = gm / NPAIR, p = gm % NPAIR;
      offF[tid] = (b*NSEQ*NSEQ + g_psF[p])*HID;
      offB[tid] = (b*NSEQ*NSEQ + g_psB[p])*HID;
      cnt[tid]  = g_pcnt[p];
    } else { offF[tid] = 0; offB[tid] = 0; cnt[tid] = 0; }
  }
  __syncthreads();

  const int arow = tid >> 1, ak = (tid & 1)*16;   // row 0..127, chunk 0/16 halves
  uint4 ra[2], rb[2];
  // prefetch k0 = 0  (k0 < 512 -> forward plane)
  {
    const __half* srcA = g_FF16 + offF[arow] + ak;
    ra[0] = *(const uint4*)srcA;
    ra[1] = *(const uint4*)(srcA + 8);
    const __half* srcB = g_WO16 + (size_t)(bn + arow)*(2*HID) + ak;
    rb[0] = *(const uint4*)srcB;
    rb[1] = *(const uint4*)(srcB + 8);
  }

  float acc[4][4][4] = {};
  for (int k0 = 0; k0 < 2*HID; k0 += 32){
    __syncthreads();
    *(uint4*)&sA[arow][ak]     = ra[0];
    *(uint4*)&sA[arow][ak + 8] = ra[1];
    *(uint4*)&sB[arow][ak]     = rb[0];
    *(uint4*)&sB[arow][ak + 8] = rb[1];
    __syncthreads();
    if (k0 + 32 < 2*HID){
      int k = k0 + 32 + ak;
      const __half* srcA = (k < HID) ? (g_FF16 + offF[arow] + k)
                                     : (g_FB16 + offB[arow] + k - HID);
      ra[0] = *(const uint4*)srcA;
      ra[1] = *(const uint4*)(srcA + 8);
      const __half* srcB = g_WO16 + (size_t)(bn + arow)*(2*HID) + k0 + 32 + ak;
      rb[0] = *(const uint4*)srcB;
      rb[1] = *(const uint4*)(srcB + 8);
    }
    #pragma unroll
    for (int ks = 0; ks < 32; ks += 16){
      uint32_t a[4][4], b[4][2];
      #pragma unroll
      for (int mt = 0; mt < 4; mt++){
        int r0 = warpM*64 + mt*16 + g;
        a[mt][0] = *(const uint32_t*)&sA[r0  ][ks + t4*2];
        a[mt][1] = *(const uint32_t*)&sA[r0+8][ks + t4*2];
        a[mt][2] = *(const uint32_t*)&sA[r0  ][ks + t4*2 + 8];
        a[mt][3] = *(const uint32_t*)&sA[r0+8][ks + t4*2 + 8];
      }
      #pragma unroll
      for (int nt = 0; nt < 4; nt++){
        int nr = warpN*32 + nt*8 + g;
        b[nt][0] = *(const uint32_t*)&sB[nr][ks + t4*2];
        b[nt][1] = *(const uint32_t*)&sB[nr][ks + t4*2 + 8];
      }
      #pragma unroll
      for (int mt = 0; mt < 4; mt++)
        #pragma unroll
        for (int nt = 0; nt < 4; nt++)
          mma16h(acc[mt][nt], a[mt], b[nt]);
    }
  }
  // epilogue: + cnt * bias
  #pragma unroll
  for (int mt = 0; mt < 4; mt++){
    int r0 = warpM*64 + mt*16 + g;
    int gm0 = bm + r0;
    float c0 = (float)cnt[r0], c1 = (float)cnt[r0+8];
    #pragma unroll
    for (int nt = 0; nt < 4; nt++){
      int gn = bn + warpN*32 + nt*8 + 2*t4;
      float bb0 = bout[gn], bb1 = bout[gn+1];
      if (gm0 < MROWS){
        out[(size_t)gm0*NOUT + gn]     = acc[mt][nt][0] + c0*bb0;
        out[(size_t)gm0*NOUT + gn + 1] = acc[mt][nt][1] + c0*bb1;
      }
      if (gm0 + 8 < MROWS){
        out[(size_t)(gm0+8)*NOUT + gn]     = acc[mt][nt][2] + c1*bb0;
        out[(size_t)(gm0+8)*NOUT + gn + 1] = acc[mt][nt][3] + c1*bb1;
      }
    }
  }
}

// ---------------- L2 normalize groups of 256 ----------------
__global__ void normalize_kernel(float* __restrict__ out)
{
  int w = blockIdx.x*8 + (threadIdx.x >> 5);
  int lane = threadIdx.x & 31;
  size_t base = (size_t)w*SEM;
  float v[8]; float ss = 0.f;
  #pragma unroll
  for (int i = 0; i < 8; i++){ v[i] = out[base + lane + 32*i]; ss += v[i]*v[i]; }
  #pragma unroll
  for (int o = 16; o; o >>= 1) ss += __shfl_xor_sync(0xffffffffu, ss, o);
  float sc = 1.f / fmaxf(sqrtf(ss), 1e-12f);
  #pragma unroll
  for (int i = 0; i < 8; i++) out[base + lane + 32*i] = v[i]*sc;
}

// ---------------- launcher ----------------
extern "C" void kernel_launch(void* const* d_in, const int* in_sizes, int n_in,
                              void* d_out, int out_size)
{
  const int*   captions = (const int*)  d_in[1];
  const int*   lengths  = (const int*)  d_in[2];
  const float* emb      = (const float*)d_in[3];
  const float* w_ih_f   = (const float*)d_in[4];
  const float* w_hh_f   = (const float*)d_in[5];
  const float* b_ih_f   = (const float*)d_in[6];
  const float* b_hh_f   = (const float*)d_in[7];
  const float* w_ih_b   = (const float*)d_in[8];
  const float* w_hh_b   = (const float*)d_in[9];
  const float* b_ih_b   = (const float*)d_in[10];
  const float* b_hh_b   = (const float*)d_in[11];
  const float* w_out    = (const float*)d_in[12];
  const float* b_out    = (const float*)d_in[13];
  float* out = (float*)d_out;

  float *wv, *Xf, *Xb;
  cudaGetSymbolAddress((void**)&wv, g_wv);
  cudaGetSymbolAddress((void**)&Xf, g_X);
  Xb = Xf + BSZ*NSEQ*G4;

  zero_state_kernel<<<(4*SB + 255)/256, 256>>>();
  setup_pairs_kernel<<<1, 256>>>();
  embed_kernel<<<BSZ*NSEQ, 256>>>(captions, lengths, emb);
  wsplit_kernel<<<(G4*HID + 255)/256, 256>>>(w_hh_f, w_hh_b);
  wout16_kernel<<<(NOUT*2*HID + 255)/256, 256>>>(w_out);

  gemm3x_bias<<<dim3(G4/128, (BSZ*NSEQ + 63)/64), 256>>>(
      wv, w_ih_f, b_ih_f, b_hh_f, Xf, BSZ*NSEQ, G4, DIM);
  gemm3x_bias<<<dim3(G4/128, (BSZ*NSEQ + 63)/64), 256>>>(
      wv, w_ih_b, b_ih_b, b_hh_b, Xb, BSZ*NSEQ, G4, DIM);

  for (int j = 0; j < NSEQ; j++)
    lstm_fused<<<dim3(HID/64, 10, 2), 256>>>(j);

  out_gemm_fp16<<<dim3(NOUT/128, (MROWS + 127)/128), 256>>>(b_out, out);
  normalize_kernel<<<(MROWS*30)/8, 256>>>(out);
}

// round 8
// speedup vs baseline: 4.2800x; 1.1109x over previous
#include <cuda_runtime.h>
#include <cuda_bf16.h>
#include <cuda_fp16.h>
#include <stdint.h>

#define BSZ 32
#define NSEQ 20
#define DIM 512
#define HID 512
#define G4 2048          // 4*HID
#define NOUT 7680        // NT*SEM
#define SEM 256
#define NPAIR 190
#define MROWS (BSZ*NPAIR)   // 6080
#define SB (NSEQ*BSZ*HID)   // 640*512 per plane
#define FSZ (BSZ*NSEQ*NSEQ*HID)

// ---------------- device scratch ----------------
__device__ float g_wv[BSZ*NSEQ*DIM];
__device__ float g_X[2][BSZ*NSEQ*G4];          // input projections (f, b)
__device__ __nv_bfloat16 g_Hh[2][2][SB];       // [dir][parity] hidden hi
__device__ __nv_bfloat16 g_Hl[2][2][SB];       // [dir][parity] hidden lo
__device__ float g_C[2][SB];                   // cell state
__device__ __nv_bfloat16 g_Wh[2][G4*HID];      // W_hh hi (f, b)
__device__ __nv_bfloat16 g_Wl[2][G4*HID];      // W_hh lo
__device__ float g_Ff[FSZ];                    // fp32 cumulative sums (recurrence use)
__device__ float g_Fb[FSZ];
__device__ __half g_FF16[FSZ];                 // fp16 cumsum planes (out GEMM)
__device__ __half g_FB16[FSZ];
__device__ __half g_WO16[NOUT*2*HID];          // fp16 w_out
__device__ int   g_psF[NPAIR];
__device__ int   g_psB[NPAIR];
__device__ int   g_pcnt[NPAIR];

__device__ __forceinline__ float sigm(float x){ return 1.f/(1.f+__expf(-x)); }

__device__ __forceinline__ uint32_t f2tf(float x){
  uint32_t r; asm("cvt.rna.tf32.f32 %0, %1;" : "=r"(r) : "f"(x)); return r;
}
__device__ __forceinline__ void mma8(float c[4], const uint32_t a[4], const uint32_t b[2]){
  asm volatile("mma.sync.aligned.m16n8k8.row.col.f32.tf32.tf32.f32 "
      "{%0,%1,%2,%3}, {%4,%5,%6,%7}, {%8,%9}, {%0,%1,%2,%3};\n"
      : "+f"(c[0]), "+f"(c[1]), "+f"(c[2]), "+f"(c[3])
      : "r"(a[0]), "r"(a[1]), "r"(a[2]), "r"(a[3]), "r"(b[0]), "r"(b[1]));
}
__device__ __forceinline__ void mma16bf(float c[4], const uint32_t a[4], const uint32_t b[2]){
  asm volatile("mma.sync.aligned.m16n8k16.row.col.f32.bf16.bf16.f32 "
      "{%0,%1,%2,%3}, {%4,%5,%6,%7}, {%8,%9}, {%0,%1,%2,%3};\n"
      : "+f"(c[0]), "+f"(c[1]), "+f"(c[2]), "+f"(c[3])
      : "r"(a[0]), "r"(a[1]), "r"(a[2]), "r"(a[3]), "r"(b[0]), "r"(b[1]));
}
__device__ __forceinline__ void mma16h(float c[4], const uint32_t a[4], const uint32_t b[2]){
  asm volatile("mma.sync.aligned.m16n8k16.row.col.f32.f16.f16.f32 "
      "{%0,%1,%2,%3}, {%4,%5,%6,%7}, {%8,%9}, {%0,%1,%2,%3};\n"
      : "+f"(c[0]), "+f"(c[1]), "+f"(c[2]), "+f"(c[3])
      : "r"(a[0]), "r"(a[1]), "r"(a[2]), "r"(a[3]), "r"(b[0]), "r"(b[1]));
}
__device__ __forceinline__ void ldsm4(uint32_t r[4], uint32_t saddr){
  asm volatile("ldmatrix.sync.aligned.m8n8.x4.shared.b16 {%0,%1,%2,%3}, [%4];"
      : "=r"(r[0]), "=r"(r[1]), "=r"(r[2]), "=r"(r[3]) : "r"(saddr));
}

// ---------------- small setup kernels ----------------
__global__ void zero_state_kernel(){
  int i = blockIdx.x*blockDim.x + threadIdx.x;
  if (i < 4*SB){
    (&g_Hh[0][0][0])[i] = __float2bfloat16(0.f);
    (&g_Hl[0][0][0])[i] = __float2bfloat16(0.f);
  }
  if (i < 2*SB) (&g_C[0][0])[i] = 0.f;
}

__global__ void wsplit_kernel(const float* __restrict__ wf, const float* __restrict__ wb){
  int i = blockIdx.x*blockDim.x + threadIdx.x;
  if (i >= G4*HID) return;
  float w = wf[i];
  __nv_bfloat16 h = __float2bfloat16(w);
  g_Wh[0][i] = h;
  g_Wl[0][i] = __float2bfloat16(w - __bfloat162float(h));
  w = wb[i];
  h = __float2bfloat16(w);
  g_Wh[1][i] = h;
  g_Wl[1][i] = __float2bfloat16(w - __bfloat162float(h));
}

__global__ void wout16_kernel(const float* __restrict__ w){
  int i = blockIdx.x*blockDim.x + threadIdx.x;
  if (i < NOUT*2*HID) g_WO16[i] = __float2half(w[i]);
}

__global__ void setup_pairs_kernel(){
  int p = threadIdx.x;
  if (p >= NPAIR) return;
  int cum = 0, k = 1, s = 0;
  for (int kk = 1; kk < NSEQ; kk++){
    int c = NSEQ - kk;
    if (p < cum + c){ k = kk; s = p - cum; break; }
    cum += c;
  }
  int e = s + k;
  g_psF[p] = s*NSEQ + e;
  g_psB[p] = e*NSEQ + s;
  g_pcnt[p] = k + 1;
}

__global__ void embed_kernel(const int* __restrict__ cap, const int* __restrict__ len,
                             const float* __restrict__ emb){
  int bt = blockIdx.x; int b = bt/NSEQ, t = bt%NSEQ;
  int tok = cap[bt];
  float m = (t < len[b]) ? 1.f : 0.f;
  const float* src = emb + (size_t)tok*DIM;
  for (int n = threadIdx.x; n < DIM; n += blockDim.x)
    g_wv[bt*DIM + n] = m * src[n];
}

// =======================================================================
// 3xTF32 GEMM (input projections)
// =======================================================================
struct S3x {
  uint32_t Ah[64][20]; uint32_t Al[64][20];
  uint32_t Bh[128][20]; uint32_t Bl[128][20];
};

__global__ void gemm3x_bias(const float* __restrict__ A, const float* __restrict__ B,
                            const float* __restrict__ b1, const float* __restrict__ b2,
                            float* __restrict__ C, int M, int N, int K)
{
  __shared__ S3x s;
  int tid = threadIdx.x;
  int lane = tid & 31, wid = tid >> 5;
  int warpM = wid >> 2, warpN = wid & 3;
  int g = lane >> 2, t = lane & 3;
  int bm = blockIdx.y*64, bn = blockIdx.x*128;
  if (bm >= M) return;
  float acc[2][4][4] = {};

  for (int k0 = 0; k0 < K; k0 += 16){
    int ar = tid >> 2, ak = (tid & 3) * 4;
    int gm = bm + ar;
    float4 av = make_float4(0.f,0.f,0.f,0.f);
    if (gm < M) av = *(const float4*)(A + (size_t)gm*K + k0 + ak);
    float4 bv[2];
    #pragma unroll
    for (int i = 0; i < 2; i++){
      int idx = tid + i*256;
      int br = idx >> 2, bk = (idx & 3) * 4;
      bv[i] = *(const float4*)(B + (size_t)(bn + br)*K + k0 + bk);
    }
    __syncthreads();
    {
      uint32_t h0=f2tf(av.x), h1=f2tf(av.y), h2=f2tf(av.z), h3=f2tf(av.w);
      s.Ah[ar][ak]=h0; s.Ah[ar][ak+1]=h1; s.Ah[ar][ak+2]=h2; s.Ah[ar][ak+3]=h3;
      s.Al[ar][ak]  =f2tf(av.x-__uint_as_float(h0));
      s.Al[ar][ak+1]=f2tf(av.y-__uint_as_float(h1));
      s.Al[ar][ak+2]=f2tf(av.z-__uint_as_float(h2));
      s.Al[ar][ak+3]=f2tf(av.w-__uint_as_float(h3));
    }
    #pragma unroll
    for (int i = 0; i < 2; i++){
      int idx = tid + i*256;
      int br = idx >> 2, bk = (idx & 3) * 4;
      uint32_t h0=f2tf(bv[i].x), h1=f2tf(bv[i].y), h2=f2tf(bv[i].z), h3=f2tf(bv[i].w);
      s.Bh[br][bk]=h0; s.Bh[br][bk+1]=h1; s.Bh[br][bk+2]=h2; s.Bh[br][bk+3]=h3;
      s.Bl[br][bk]  =f2tf(bv[i].x-__uint_as_float(h0));
      s.Bl[br][bk+1]=f2tf(bv[i].y-__uint_as_float(h1));
      s.Bl[br][bk+2]=f2tf(bv[i].z-__uint_as_float(h2));
      s.Bl[br][bk+3]=f2tf(bv[i].w-__uint_as_float(h3));
    }
    __syncthreads();
    #pragma unroll
    for (int ks = 0; ks < 16; ks += 8){
      uint32_t ah[2][4], al[2][4], bh[4][2], bl[4][2];
      #pragma unroll
      for (int mt = 0; mt < 2; mt++){
        int m = warpM*32 + mt*16 + g;
        int k = ks + t;
        ah[mt][0]=s.Ah[m][k];   ah[mt][1]=s.Ah[m+8][k];
        ah[mt][2]=s.Ah[m][k+4]; ah[mt][3]=s.Ah[m+8][k+4];
        al[mt][0]=s.Al[m][k];   al[mt][1]=s.Al[m+8][k];
        al[mt][2]=s.Al[m][k+4]; al[mt][3]=s.Al[m+8][k+4];
      }
      #pragma unroll
      for (int nt = 0; nt < 4; nt++){
        int n = warpN*32 + nt*8 + g;
        bh[nt][0]=s.Bh[n][ks+t]; bh[nt][1]=s.Bh[n][ks+t+4];
        bl[nt][0]=s.Bl[n][ks+t]; bl[nt][1]=s.Bl[n][ks+t+4];
      }
      #pragma unroll
      for (int mt = 0; mt < 2; mt++)
        #pragma unroll
        for (int nt = 0; nt < 4; nt++){
          mma8(acc[mt][nt], ah[mt], bh[nt]);
          mma8(acc[mt][nt], al[mt], bh[nt]);
          mma8(acc[mt][nt], ah[mt], bl[nt]);
        }
    }
    __syncthreads();
  }
  #pragma unroll
  for (int mt = 0; mt < 2; mt++){
    int r0 = bm + warpM*32 + mt*16 + g;
    #pragma unroll
    for (int nt = 0; nt < 4; nt++){
      int gn = bn + warpN*32 + nt*8 + 2*t;
      float e0 = b1[gn] + b2[gn], e1 = b1[gn+1] + b2[gn+1];
      if (r0 < M){
        C[(size_t)r0*N + gn]     = acc[mt][nt][0] + e0;
        C[(size_t)r0*N + gn + 1] = acc[mt][nt][1] + e1;
      }
      if (r0 + 8 < M){
        C[(size_t)(r0+8)*N + gn]     = acc[mt][nt][2] + e0;
        C[(size_t)(r0+8)*N + gn + 1] = acc[mt][nt][3] + e1;
      }
    }
  }
}

// =======================================================================
// Fused LSTM step: 3xBF16 recurrent GEMM (ldmatrix frags) + gates + F cumsum
// smem rows stride 24 halves (48B = 12 words): conflict-free LDSM phases
// =======================================================================
__global__ void lstm_fused(int j)
{
  const int dir = blockIdx.z;
  const int n0 = blockIdx.x * 64;
  const int p = j & 1;
  int bm, rowLim;
  if (dir == 0){
    rowLim = (j+1)*BSZ;
    bm = blockIdx.y * 64;
    if (bm >= rowLim) return;
  } else {
    rowLim = NSEQ*BSZ;
    bm = j*BSZ + blockIdx.y*64;
    if (bm >= rowLim) return;
  }
  const __nv_bfloat16* __restrict__ Ah = g_Hh[dir][p];
  const __nv_bfloat16* __restrict__ Al = g_Hl[dir][p];
  const __nv_bfloat16* __restrict__ Wh = g_Wh[dir];
  const __nv_bfloat16* __restrict__ Wl = g_Wl[dir];

  __shared__ __align__(16) uint16_t sA[2][64][24];   // plane stride 3072 B
  __shared__ __align__(16) uint16_t sB[2][256][24];  // plane stride 12288 B

  const int tid = threadIdx.x, lane = tid & 31, wid = tid >> 5;
  const int warpM = wid & 3, warpN = wid >> 2;
  const int g8 = lane >> 2, t4 = lane & 3;

  // ldmatrix lane addressing
  const uint32_t sAu = (uint32_t)__cvta_generic_to_shared(&sA[0][0][0]);
  const uint32_t sBu = (uint32_t)__cvta_generic_to_shared(&sB[0][0][0]);
  const int bmat = lane >> 3;
  const uint32_t aOff = ((uint32_t)(warpM*16 + (lane & 15))*24 + (uint32_t)(lane >> 4)*8)*2;
  const uint32_t bOff = ((uint32_t)(warpN*32 + ((bmat >> 1)*8) + (lane & 7))*24
                        + (uint32_t)(bmat & 1)*8)*2;

  float acc[4][4][4] = {};

  uint4 ra[2]; uint4 rb[2][2];
  const int arow = tid >> 1, ak8 = (tid & 1)*8;

  {
    if (tid < 128){
      int gr = bm + arow;
      if (gr < rowLim){
        ra[0] = *(const uint4*)(Ah + (size_t)gr*HID + ak8);
        ra[1] = *(const uint4*)(Al + (size_t)gr*HID + ak8);
      } else { ra[0] = make_uint4(0,0,0,0); ra[1] = ra[0]; }
    }
    #pragma unroll
    for (int s = 0; s < 2; s++){
      int i = tid + s*256;
      int rbr = i >> 1, k8 = (i & 1)*8;
      int wrow = (rbr >> 6)*HID + n0 + (rbr & 63);
      rb[s][0] = *(const uint4*)(Wh + (size_t)wrow*HID + k8);
      rb[s][1] = *(const uint4*)(Wl + (size_t)wrow*HID + k8);
    }
  }

  for (int k0 = 0; k0 < HID; k0 += 16){
    __syncthreads();
    if (tid < 128){
      *(uint4*)&sA[0][arow][ak8] = ra[0];
      *(uint4*)&sA[1][arow][ak8] = ra[1];
    }
    #pragma unroll
    for (int s = 0; s < 2; s++){
      int i = tid + s*256;
      int rbr = i >> 1, k8 = (i & 1)*8;
      *(uint4*)&sB[0][rbr][k8] = rb[s][0];
      *(uint4*)&sB[1][rbr][k8] = rb[s][1];
    }
    __syncthreads();
    if (k0 + 16 < HID){
      int kn = k0 + 16;
      if (tid < 128){
        int gr = bm + arow;
        if (gr < rowLim){
          ra[0] = *(const uint4*)(Ah + (size_t)gr*HID + kn + ak8);
          ra[1] = *(const uint4*)(Al + (size_t)gr*HID + kn + ak8);
        } else { ra[0] = make_uint4(0,0,0,0); ra[1] = ra[0]; }
      }
      #pragma unroll
      for (int s = 0; s < 2; s++){
        int i = tid + s*256;
        int rbr = i >> 1, k8 = (i & 1)*8;
        int wrow = (rbr >> 6)*HID + n0 + (rbr & 63);
        rb[s][0] = *(const uint4*)(Wh + (size_t)wrow*HID + kn + k8);
        rb[s][1] = *(const uint4*)(Wl + (size_t)wrow*HID + kn + k8);
      }
    }
    uint32_t afh[4], afl[4];
    ldsm4(afh, sAu + aOff);
    ldsm4(afl, sAu + 3072 + aOff);
    #pragma unroll
    for (int g = 0; g < 4; g++){
      uint32_t bh[2][4], bl[2][4];
      uint32_t base = sBu + (uint32_t)g*64*48 + bOff;
      ldsm4(bh[0], base);
      ldsm4(bh[1], base + 16*48);
      ldsm4(bl[0], base + 12288);
      ldsm4(bl[1], base + 12288 + 16*48);
      #pragma unroll
      for (int nt = 0; nt < 4; nt++){
        mma16bf(acc[g][nt], afh, &bh[nt>>1][(nt&1)*2]);
        mma16bf(acc[g][nt], afl, &bh[nt>>1][(nt&1)*2]);
        mma16bf(acc[g][nt], afh, &bl[nt>>1][(nt&1)*2]);
      }
    }
  }

  // ---- epilogue ----
  const float* __restrict__ X = g_X[dir];
  float* __restrict__ C = g_C[dir];
  __nv_bfloat16* __restrict__ Hh = g_Hh[dir][p^1];
  __nv_bfloat16* __restrict__ Hl = g_Hl[dir][p^1];
  float* __restrict__ F  = dir ? g_Fb  : g_Ff;
  __half* __restrict__ F16 = dir ? g_FB16 : g_FF16;

  #pragma unroll
  for (int rr = 0; rr < 2; rr++){
    int gm = bm + warpM*16 + g8 + rr*8;
    if (gm >= rowLim) continue;
    int chain = gm >> 5, b = gm & 31;
    int t = dir ? (chain - j) : j;
    size_t xrow = (size_t)(b*NSEQ + t)*G4;
    size_t fbase;
    bool first;
    if (dir == 0){ fbase = ((size_t)(b*NSEQ + chain)*NSEQ + j)*HID; first = (j == chain); }
    else         { fbase = ((size_t)(b*NSEQ + chain)*NSEQ + t)*HID; first = (t == chain); }
    #pragma unroll
    for (int nt = 0; nt < 4; nt++){
      #pragma unroll
      for (int cc = 0; cc < 2; cc++){
        int n = n0 + warpN*32 + nt*8 + t4*2 + cc;
        int ai = rr*2 + cc;
        float gi = acc[0][nt][ai] + X[xrow + n];
        float gf = acc[1][nt][ai] + X[xrow + 512 + n];
        float gc = acc[2][nt][ai] + X[xrow + 1024 + n];
        float go = acc[3][nt][ai] + X[xrow + 1536 + n];
        size_t si = (size_t)gm*HID + n;
        float c = sigm(gf)*C[si] + sigm(gi)*tanhf(gc);
        float h = sigm(go)*tanhf(c);
        C[si] = c;
        __nv_bfloat16 hh = __float2bfloat16(h);
        Hh[si] = hh;
        Hl[si] = __float2bfloat16(h - __bfloat162float(hh));
        float prev = first ? 0.f : F[fbase + n + (dir ? (int)HID : -(int)HID)];
        float v = prev + h;
        F[fbase + n]   = v;
        F16[fbase + n] = __float2half(v);
      }
    }
  }
}

// =======================================================================
// out GEMM: single-pass FP16 m16n8k16 with ldmatrix frags.
// M=6080 (gathered), N=7680, K=1024. BM=BN=128, BK=32, 256 threads.
// smem row stride 40 halves (80B = 20 words): conflict-free LDSM phases.
// =======================================================================
__global__ __launch_bounds__(256) void out_gemm_fp16(const float* __restrict__ bout,
                                                     float* __restrict__ out)
{
  __shared__ __align__(16) __half sA[128][40];
  __shared__ __align__(16) __half sB[128][40];
  __shared__ int offF[128], offB[128], cnt[128];
  const int tid = threadIdx.x, lane = tid & 31, wid = tid >> 5;
  const int warpM = wid >> 2, warpN = wid & 3;
  const int g = lane >> 2, t4 = lane & 3;
  const int bm = blockIdx.y*128, bn = blockIdx.x*128;

  if (tid < 128){
    int gm = bm + tid;
    if (gm < MROWS){
      int b = gm / NPAIR, p = gm % NPAIR;
      offF[tid] = (b*NSEQ*NSEQ + g_psF[p])*HID;
      offB[tid] = (b*NSEQ*NSEQ + g_psB[p])*HID;
      cnt[tid]  = g_pcnt[p];
    } else { offF[tid] = 0; offB[tid] = 0; cnt[tid] = 0; }
  }
  __syncthreads();

  const uint32_t sAu = (uint32_t)__cvta_generic_to_shared(&sA[0][0]);
  const uint32_t sBu = (uint32_t)__cvta_generic_to_shared(&sB[0][0]);
  const int bmat = lane >> 3;
  const uint32_t aOff = ((uint32_t)(warpM*64 + (lane & 15))*40 + (uint32_t)(lane >> 4)*8)*2;
  const uint32_t bOff = ((uint32_t)(warpN*32 + ((bmat >> 1)*8) + (lane & 7))*40
                        + (uint32_t)(bmat & 1)*8)*2;

  const int arow = tid >> 1, ak = (tid & 1)*16;
  uint4 ra[2], rb[2];
  {
    const __half* srcA = g_FF16 + offF[arow] + ak;
    ra[0] = *(const uint4*)srcA;
    ra[1] = *(const uint4*)(srcA + 8);
    const __half* srcB = g_WO16 + (size_t)(bn + arow)*(2*HID) + ak;
    rb[0] = *(const uint4*)srcB;
    rb[1] = *(const uint4*)(srcB + 8);
  }

  float acc[4][4][4] = {};
  for (int k0 = 0; k0 < 2*HID; k0 += 32){
    __syncthreads();
    *(uint4*)&sA[arow][ak]     = ra[0];
    *(uint4*)&sA[arow][ak + 8] = ra[1];
    *(uint4*)&sB[arow][ak]     = rb[0];
    *(uint4*)&sB[arow][ak + 8] = rb[1];
    __syncthreads();
    if (k0 + 32 < 2*HID){
      int k = k0 + 32 + ak;
      const __half* srcA = (k < HID) ? (g_FF16 + offF[arow] + k)
                                     : (g_FB16 + offB[arow] + k - HID);
      ra[0] = *(const uint4*)srcA;
      ra[1] = *(const uint4*)(srcA + 8);
      const __half* srcB = g_WO16 + (size_t)(bn + arow)*(2*HID) + k0 + 32 + ak;
      rb[0] = *(const uint4*)srcB;
      rb[1] = *(const uint4*)(srcB + 8);
    }
    #pragma unroll
    for (int ks = 0; ks < 32; ks += 16){
      uint32_t a[4][4], bq[2][4];
      #pragma unroll
      for (int mt = 0; mt < 4; mt++)
        ldsm4(a[mt], sAu + aOff + (uint32_t)mt*16*80 + (uint32_t)ks*2);
      ldsm4(bq[0], sBu + bOff + (uint32_t)ks*2);
      ldsm4(bq[1], sBu + bOff + 16*80 + (uint32_t)ks*2);
      #pragma unroll
      for (int mt = 0; mt < 4; mt++)
        #pragma unroll
        for (int nt = 0; nt < 4; nt++)
          mma16h(acc[mt][nt], a[mt], &bq[nt>>1][(nt&1)*2]);
    }
  }
  // epilogue: + cnt * bias
  #pragma unroll
  for (int mt = 0; mt < 4; mt++){
    int r0 = warpM*64 + mt*16 + g;
    int gm0 = bm + r0;
    float c0 = (float)cnt[r0], c1 = (float)cnt[r0+8];
    #pragma unroll
    for (int nt = 0; nt < 4; nt++){
      int gn = bn + warpN*32 + nt*8 + 2*t4;
      float bb0 = bout[gn], bb1 = bout[gn+1];
      if (gm0 < MROWS){
        out[(size_t)gm0*NOUT + gn]     = acc[mt][nt][0] + c0*bb0;
        out[(size_t)gm0*NOUT + gn + 1] = acc[mt][nt][1] + c0*bb1;
      }
      if (gm0 + 8 < MROWS){
        out[(size_t)(gm0+8)*NOUT + gn]     = acc[mt][nt][2] + c1*bb0;
        out[(size_t)(gm0+8)*NOUT + gn + 1] = acc[mt][nt][3] + c1*bb1;
      }
    }
  }
}

// ---------------- L2 normalize groups of 256 ----------------
__global__ void normalize_kernel(float* __restrict__ out)
{
  int w = blockIdx.x*8 + (threadIdx.x >> 5);
  int lane = threadIdx.x & 31;
  size_t base = (size_t)w*SEM;
  float v[8]; float ss = 0.f;
  #pragma unroll
  for (int i = 0; i < 8; i++){ v[i] = out[base + lane + 32*i]; ss += v[i]*v[i]; }
  #pragma unroll
  for (int o = 16; o; o >>= 1) ss += __shfl_xor_sync(0xffffffffu, ss, o);
  float sc = 1.f / fmaxf(sqrtf(ss), 1e-12f);
  #pragma unroll
  for (int i = 0; i < 8; i++) out[base + lane + 32*i] = v[i]*sc;
}

// ---------------- launcher ----------------
extern "C" void kernel_launch(void* const* d_in, const int* in_sizes, int n_in,
                              void* d_out, int out_size)
{
  const int*   captions = (const int*)  d_in[1];
  const int*   lengths  = (const int*)  d_in[2];
  const float* emb      = (const float*)d_in[3];
  const float* w_ih_f   = (const float*)d_in[4];
  const float* w_hh_f   = (const float*)d_in[5];
  const float* b_ih_f   = (const float*)d_in[6];
  const float* b_hh_f   = (const float*)d_in[7];
  const float* w_ih_b   = (const float*)d_in[8];
  const float* w_hh_b   = (const float*)d_in[9];
  const float* b_ih_b   = (const float*)d_in[10];
  const float* b_hh_b   = (const float*)d_in[11];
  const float* w_out    = (const float*)d_in[12];
  const float* b_out    = (const float*)d_in[13];
  float* out = (float*)d_out;

  float *wv, *Xf, *Xb;
  cudaGetSymbolAddress((void**)&wv, g_wv);
  cudaGetSymbolAddress((void**)&Xf, g_X);
  Xb = Xf + BSZ*NSEQ*G4;

  zero_state_kernel<<<(4*SB + 255)/256, 256>>>();
  setup_pairs_kernel<<<1, 256>>>();
  embed_kernel<<<BSZ*NSEQ, 256>>>(captions, lengths, emb);
  wsplit_kernel<<<(G4*HID + 255)/256, 256>>>(w_hh_f, w_hh_b);
  wout16_kernel<<<(NOUT*2*HID + 255)/256, 256>>>(w_out);

  gemm3x_bias<<<dim3(G4/128, (BSZ*NSEQ + 63)/64), 256>>>(
      wv, w_ih_f, b_ih_f, b_hh_f, Xf, BSZ*NSEQ, G4, DIM);
  gemm3x_bias<<<dim3(G4/128, (BSZ*NSEQ + 63)/64), 256>>>(
      wv, w_ih_b, b_ih_b, b_hh_b, Xb, BSZ*NSEQ, G4, DIM);

  for (int j = 0; j < NSEQ; j++)
    lstm_fused<<<dim3(HID/64, 10, 2), 256>>>(j);

  out_gemm_fp16<<<dim3(NOUT/128, (MROWS + 127)/128), 256>>>(b_out, out);
  normalize_kernel<<<(MROWS*30)/8, 256>>>(out);
}

// round 9
// speedup vs baseline: 5.4788x; 1.2801x over previous
#include <cuda_runtime.h>
#include <cuda_bf16.h>
#include <cuda_fp16.h>
#include <stdint.h>

#define BSZ 32
#define NSEQ 20
#define DIM 512
#define HID 512
#define G4 2048          // 4*HID
#define NOUT 7680        // NT*SEM
#define SEM 256
#define NPAIR 190
#define MROWS (BSZ*NPAIR)   // 6080
#define SB (NSEQ*BSZ*HID)   // 640*512 per plane
#define FSZ (BSZ*NSEQ*NSEQ*HID)

// ---------------- device scratch ----------------
__device__ float g_wv[BSZ*NSEQ*DIM];
__device__ float g_X[2][BSZ*NSEQ*G4];          // input projections (f, b)
__device__ __half g_H16[2][2][SB];             // [dir][parity] hidden (fp16)
__device__ float g_C[2][SB];                   // cell state
__device__ __half g_W16[2][G4*HID];            // W_hh fp16 (f, b)
__device__ float g_Ff[FSZ];                    // fp32 cumulative sums (recurrence use)
__device__ float g_Fb[FSZ];
__device__ __half g_FF16[FSZ];                 // fp16 cumsum planes (out GEMM)
__device__ __half g_FB16[FSZ];
__device__ __half g_WO16[NOUT*2*HID];          // fp16 w_out
__device__ int   g_psF[NPAIR];
__device__ int   g_psB[NPAIR];
__device__ int   g_pcnt[NPAIR];

__device__ __forceinline__ float sigm(float x){ return 1.f/(1.f+__expf(-x)); }

__device__ __forceinline__ uint32_t f2tf(float x){
  uint32_t r; asm("cvt.rna.tf32.f32 %0, %1;" : "=r"(r) : "f"(x)); return r;
}
__device__ __forceinline__ void mma8(float c[4], const uint32_t a[4], const uint32_t b[2]){
  asm volatile("mma.sync.aligned.m16n8k8.row.col.f32.tf32.tf32.f32 "
      "{%0,%1,%2,%3}, {%4,%5,%6,%7}, {%8,%9}, {%0,%1,%2,%3};\n"
      : "+f"(c[0]), "+f"(c[1]), "+f"(c[2]), "+f"(c[3])
      : "r"(a[0]), "r"(a[1]), "r"(a[2]), "r"(a[3]), "r"(b[0]), "r"(b[1]));
}
__device__ __forceinline__ void mma16h(float c[4], const uint32_t a[4], const uint32_t b[2]){
  asm volatile("mma.sync.aligned.m16n8k16.row.col.f32.f16.f16.f32 "
      "{%0,%1,%2,%3}, {%4,%5,%6,%7}, {%8,%9}, {%0,%1,%2,%3};\n"
      : "+f"(c[0]), "+f"(c[1]), "+f"(c[2]), "+f"(c[3])
      : "r"(a[0]), "r"(a[1]), "r"(a[2]), "r"(a[3]), "r"(b[0]), "r"(b[1]));
}
__device__ __forceinline__ void ldsm4(uint32_t r[4], uint32_t saddr){
  asm volatile("ldmatrix.sync.aligned.m8n8.x4.shared.b16 {%0,%1,%2,%3}, [%4];"
      : "=r"(r[0]), "=r"(r[1]), "=r"(r[2]), "=r"(r[3]) : "r"(saddr));
}

// ---------------- small setup kernels ----------------
__global__ void zero_state_kernel(){
  int i = blockIdx.x*blockDim.x + threadIdx.x;
  if (i < 4*SB) (&g_H16[0][0][0])[i] = __float2half(0.f);
  if (i < 2*SB) (&g_C[0][0])[i] = 0.f;
}

__global__ void whh16_kernel(const float* __restrict__ wf, const float* __restrict__ wb){
  int i = blockIdx.x*blockDim.x + threadIdx.x;
  if (i >= G4*HID) return;
  g_W16[0][i] = __float2half(wf[i]);
  g_W16[1][i] = __float2half(wb[i]);
}

__global__ void wout16_kernel(const float* __restrict__ w){
  int i = blockIdx.x*blockDim.x + threadIdx.x;
  if (i < NOUT*2*HID) g_WO16[i] = __float2half(w[i]);
}

__global__ void setup_pairs_kernel(){
  int p = threadIdx.x;
  if (p >= NPAIR) return;
  int cum = 0, k = 1, s = 0;
  for (int kk = 1; kk < NSEQ; kk++){
    int c = NSEQ - kk;
    if (p < cum + c){ k = kk; s = p - cum; break; }
    cum += c;
  }
  int e = s + k;
  g_psF[p] = s*NSEQ + e;
  g_psB[p] = e*NSEQ + s;
  g_pcnt[p] = k + 1;
}

__global__ void embed_kernel(const int* __restrict__ cap, const int* __restrict__ len,
                             const float* __restrict__ emb){
  int bt = blockIdx.x; int b = bt/NSEQ, t = bt%NSEQ;
  int tok = cap[bt];
  float m = (t < len[b]) ? 1.f : 0.f;
  const float* src = emb + (size_t)tok*DIM;
  for (int n = threadIdx.x; n < DIM; n += blockDim.x)
    g_wv[bt*DIM + n] = m * src[n];
}

// =======================================================================
// 3xTF32 GEMM (input projections)
// =======================================================================
struct S3x {
  uint32_t Ah[64][20]; uint32_t Al[64][20];
  uint32_t Bh[128][20]; uint32_t Bl[128][20];
};

__global__ void gemm3x_bias(const float* __restrict__ A, const float* __restrict__ B,
                            const float* __restrict__ b1, const float* __restrict__ b2,
                            float* __restrict__ C, int M, int N, int K)
{
  __shared__ S3x s;
  int tid = threadIdx.x;
  int lane = tid & 31, wid = tid >> 5;
  int warpM = wid >> 2, warpN = wid & 3;
  int g = lane >> 2, t = lane & 3;
  int bm = blockIdx.y*64, bn = blockIdx.x*128;
  if (bm >= M) return;
  float acc[2][4][4] = {};

  for (int k0 = 0; k0 < K; k0 += 16){
    int ar = tid >> 2, ak = (tid & 3) * 4;
    int gm = bm + ar;
    float4 av = make_float4(0.f,0.f,0.f,0.f);
    if (gm < M) av = *(const float4*)(A + (size_t)gm*K + k0 + ak);
    float4 bv[2];
    #pragma unroll
    for (int i = 0; i < 2; i++){
      int idx = tid + i*256;
      int br = idx >> 2, bk = (idx & 3) * 4;
      bv[i] = *(const float4*)(B + (size_t)(bn + br)*K + k0 + bk);
    }
    __syncthreads();
    {
      uint32_t h0=f2tf(av.x), h1=f2tf(av.y), h2=f2tf(av.z), h3=f2tf(av.w);
      s.Ah[ar][ak]=h0; s.Ah[ar][ak+1]=h1; s.Ah[ar][ak+2]=h2; s.Ah[ar][ak+3]=h3;
      s.Al[ar][ak]  =f2tf(av.x-__uint_as_float(h0));
      s.Al[ar][ak+1]=f2tf(av.y-__uint_as_float(h1));
      s.Al[ar][ak+2]=f2tf(av.z-__uint_as_float(h2));
      s.Al[ar][ak+3]=f2tf(av.w-__uint_as_float(h3));
    }
    #pragma unroll
    for (int i = 0; i < 2; i++){
      int idx = tid + i*256;
      int br = idx >> 2, bk = (idx & 3) * 4;
      uint32_t h0=f2tf(bv[i].x), h1=f2tf(bv[i].y), h2=f2tf(bv[i].z), h3=f2tf(bv[i].w);
      s.Bh[br][bk]=h0; s.Bh[br][bk+1]=h1; s.Bh[br][bk+2]=h2; s.Bh[br][bk+3]=h3;
      s.Bl[br][bk]  =f2tf(bv[i].x-__uint_as_float(h0));
      s.Bl[br][bk+1]=f2tf(bv[i].y-__uint_as_float(h1));
      s.Bl[br][bk+2]=f2tf(bv[i].z-__uint_as_float(h2));
      s.Bl[br][bk+3]=f2tf(bv[i].w-__uint_as_float(h3));
    }
    __syncthreads();
    #pragma unroll
    for (int ks = 0; ks < 16; ks += 8){
      uint32_t ah[2][4], al[2][4], bh[4][2], bl[4][2];
      #pragma unroll
      for (int mt = 0; mt < 2; mt++){
        int m = warpM*32 + mt*16 + g;
        int k = ks + t;
        ah[mt][0]=s.Ah[m][k];   ah[mt][1]=s.Ah[m+8][k];
        ah[mt][2]=s.Ah[m][k+4]; ah[mt][3]=s.Ah[m+8][k+4];
        al[mt][0]=s.Al[m][k];   al[mt][1]=s.Al[m+8][k];
        al[mt][2]=s.Al[m][k+4]; al[mt][3]=s.Al[m+8][k+4];
      }
      #pragma unroll
      for (int nt = 0; nt < 4; nt++){
        int n = warpN*32 + nt*8 + g;
        bh[nt][0]=s.Bh[n][ks+t]; bh[nt][1]=s.Bh[n][ks+t+4];
        bl[nt][0]=s.Bl[n][ks+t]; bl[nt][1]=s.Bl[n][ks+t+4];
      }
      #pragma unroll
      for (int mt = 0; mt < 2; mt++)
        #pragma unroll
        for (int nt = 0; nt < 4; nt++){
          mma8(acc[mt][nt], ah[mt], bh[nt]);
          mma8(acc[mt][nt], al[mt], bh[nt]);
          mma8(acc[mt][nt], ah[mt], bl[nt]);
        }
    }
    __syncthreads();
  }
  #pragma unroll
  for (int mt = 0; mt < 2; mt++){
    int r0 = bm + warpM*32 + mt*16 + g;
    #pragma unroll
    for (int nt = 0; nt < 4; nt++){
      int gn = bn + warpN*32 + nt*8 + 2*t;
      float e0 = b1[gn] + b2[gn], e1 = b1[gn+1] + b2[gn+1];
      if (r0 < M){
        C[(size_t)r0*N + gn]     = acc[mt][nt][0] + e0;
        C[(size_t)r0*N + gn + 1] = acc[mt][nt][1] + e1;
      }
      if (r0 + 8 < M){
        C[(size_t)(r0+8)*N + gn]     = acc[mt][nt][2] + e0;
        C[(size_t)(r0+8)*N + gn + 1] = acc[mt][nt][3] + e1;
      }
    }
  }
}

// =======================================================================
// Fused LSTM step: single-pass FP16 recurrent GEMM (ldmatrix frags)
//                  + gates + state + F cumsum
// smem rows stride 24 halves (48B = 12 words): conflict-free LDSM phases
// =======================================================================
__global__ void lstm_fused(int j)
{
  const int dir = blockIdx.z;
  const int n0 = blockIdx.x * 64;
  const int p = j & 1;
  int bm, rowLim;
  if (dir == 0){
    rowLim = (j+1)*BSZ;
    bm = blockIdx.y * 64;
    if (bm >= rowLim) return;
  } else {
    rowLim = NSEQ*BSZ;
    bm = j*BSZ + blockIdx.y*64;
    if (bm >= rowLim) return;
  }
  const __half* __restrict__ Ain = g_H16[dir][p];
  const __half* __restrict__ W = g_W16[dir];

  __shared__ __align__(16) uint16_t sA[64][24];    // 3072 B
  __shared__ __align__(16) uint16_t sB[256][24];   // 12288 B

  const int tid = threadIdx.x, lane = tid & 31, wid = tid >> 5;
  const int warpM = wid & 3, warpN = wid >> 2;
  const int g8 = lane >> 2, t4 = lane & 3;

  // ldmatrix lane addressing
  const uint32_t sAu = (uint32_t)__cvta_generic_to_shared(&sA[0][0]);
  const uint32_t sBu = (uint32_t)__cvta_generic_to_shared(&sB[0][0]);
  const int bmat = lane >> 3;
  const uint32_t aOff = ((uint32_t)(warpM*16 + (lane & 15))*24 + (uint32_t)(lane >> 4)*8)*2;
  const uint32_t bOff = ((uint32_t)(warpN*32 + ((bmat >> 1)*8) + (lane & 7))*24
                        + (uint32_t)(bmat & 1)*8)*2;

  float acc[4][4][4] = {};

  uint4 ra; uint4 rb[2];
  const int arow = tid >> 1, ak8 = (tid & 1)*8;

  {
    if (tid < 128){
      int gr = bm + arow;
      ra = (gr < rowLim) ? *(const uint4*)(Ain + (size_t)gr*HID + ak8)
                         : make_uint4(0,0,0,0);
    }
    #pragma unroll
    for (int s = 0; s < 2; s++){
      int i = tid + s*256;
      int rbr = i >> 1, k8 = (i & 1)*8;
      int wrow = (rbr >> 6)*HID + n0 + (rbr & 63);
      rb[s] = *(const uint4*)(W + (size_t)wrow*HID + k8);
    }
  }

  for (int k0 = 0; k0 < HID; k0 += 16){
    __syncthreads();
    if (tid < 128) *(uint4*)&sA[arow][ak8] = ra;
    #pragma unroll
    for (int s = 0; s < 2; s++){
      int i = tid + s*256;
      int rbr = i >> 1, k8 = (i & 1)*8;
      *(uint4*)&sB[rbr][k8] = rb[s];
    }
    __syncthreads();
    if (k0 + 16 < HID){
      int kn = k0 + 16;
      if (tid < 128){
        int gr = bm + arow;
        ra = (gr < rowLim) ? *(const uint4*)(Ain + (size_t)gr*HID + kn + ak8)
                           : make_uint4(0,0,0,0);
      }
      #pragma unroll
      for (int s = 0; s < 2; s++){
        int i = tid + s*256;
        int rbr = i >> 1, k8 = (i & 1)*8;
        int wrow = (rbr >> 6)*HID + n0 + (rbr & 63);
        rb[s] = *(const uint4*)(W + (size_t)wrow*HID + kn + k8);
      }
    }
    uint32_t af[4];
    ldsm4(af, sAu + aOff);
    #pragma unroll
    for (int g = 0; g < 4; g++){
      uint32_t bq[2][4];
      uint32_t base = sBu + (uint32_t)g*64*48 + bOff;
      ldsm4(bq[0], base);
      ldsm4(bq[1], base + 16*48);
      #pragma unroll
      for (int nt = 0; nt < 4; nt++)
        mma16h(acc[g][nt], af, &bq[nt>>1][(nt&1)*2]);
    }
  }

  // ---- epilogue ----
  const float* __restrict__ X = g_X[dir];
  float* __restrict__ C = g_C[dir];
  __half* __restrict__ Hn = g_H16[dir][p^1];
  float* __restrict__ F  = dir ? g_Fb  : g_Ff;
  __half* __restrict__ F16 = dir ? g_FB16 : g_FF16;

  #pragma unroll
  for (int rr = 0; rr < 2; rr++){
    int gm = bm + warpM*16 + g8 + rr*8;
    if (gm >= rowLim) continue;
    int chain = gm >> 5, b = gm & 31;
    int t = dir ? (chain - j) : j;
    size_t xrow = (size_t)(b*NSEQ + t)*G4;
    size_t fbase;
    bool first;
    if (dir == 0){ fbase = ((size_t)(b*NSEQ + chain)*NSEQ + j)*HID; first = (j == chain); }
    else         { fbase = ((size_t)(b*NSEQ + chain)*NSEQ + t)*HID; first = (t == chain); }
    #pragma unroll
    for (int nt = 0; nt < 4; nt++){
      #pragma unroll
      for (int cc = 0; cc < 2; cc++){
        int n = n0 + warpN*32 + nt*8 + t4*2 + cc;
        int ai = rr*2 + cc;
        float gi = acc[0][nt][ai] + X[xrow + n];
        float gf = acc[1][nt][ai] + X[xrow + 512 + n];
        float gc = acc[2][nt][ai] + X[xrow + 1024 + n];
        float go = acc[3][nt][ai] + X[xrow + 1536 + n];
        size_t si = (size_t)gm*HID + n;
        float c = sigm(gf)*C[si] + sigm(gi)*tanhf(gc);
        float h = sigm(go)*tanhf(c);
        C[si] = c;
        Hn[si] = __float2half(h);
        float prev = first ? 0.f : F[fbase + n + (dir ? (int)HID : -(int)HID)];
        float v = prev + h;
        F[fbase + n]   = v;
        F16[fbase + n] = __float2half(v);
      }
    }
  }
}

// =======================================================================
// out GEMM: single-pass FP16 m16n8k16 with ldmatrix frags.
// M=6080 (gathered), N=7680, K=1024. BM=BN=128, BK=32, 256 threads.
// smem row stride 40 halves (80B = 20 words): conflict-free LDSM phases.
// =======================================================================
__global__ __launch_bounds__(256) void out_gemm_fp16(const float* __restrict__ bout,
                                                     float* __restrict__ out)
{
  __shared__ __align__(16) __half sA[128][40];
  __shared__ __align__(16) __half sB[128][40];
  __shared__ int offF[128], offB[128], cnt[128];
  const int tid = threadIdx.x, lane = tid & 31, wid = tid >> 5;
  const int warpM = wid >> 2, warpN = wid & 3;
  const int g = lane >> 2, t4 = lane & 3;
  const int bm = blockIdx.y*128, bn = blockIdx.x*128;

  if (tid < 128){
    int gm = bm + tid;
    if (gm < MROWS){
      int b = gm / NPAIR, p = gm % NPAIR;
      offF[tid] = (b*NSEQ*NSEQ + g_psF[p])*HID;
      offB[tid] = (b*NSEQ*NSEQ + g_psB[p])*HID;
      cnt[tid]  = g_pcnt[p];
    } else { offF[tid] = 0; offB[tid] = 0; cnt[tid] = 0; }
  }
  __syncthreads();

  const uint32_t sAu = (uint32_t)__cvta_generic_to_shared(&sA[0][0]);
  const uint32_t sBu = (uint32_t)__cvta_generic_to_shared(&sB[0][0]);
  const int bmat = lane >> 3;
  const uint32_t aOff = ((uint32_t)(warpM*64 + (lane & 15))*40 + (uint32_t)(lane >> 4)*8)*2;
  const uint32_t bOff = ((uint32_t)(warpN*32 + ((bmat >> 1)*8) + (lane & 7))*40
                        + (uint32_t)(bmat & 1)*8)*2;

  const int arow = tid >> 1, ak = (tid & 1)*16;
  uint4 ra[2], rb[2];
  {
    const __half* srcA = g_FF16 + offF[arow] + ak;
    ra[0] = *(const uint4*)srcA;
    ra[1] = *(const uint4*)(srcA + 8);
    const __half* srcB = g_WO16 + (size_t)(bn + arow)*(2*HID) + ak;
    rb[0] = *(const uint4*)srcB;
    rb[1] = *(const uint4*)(srcB + 8);
  }

  float acc[4][4][4] = {};
  for (int k0 = 0; k0 < 2*HID; k0 += 32){
    __syncthreads();
    *(uint4*)&sA[arow][ak]     = ra[0];
    *(uint4*)&sA[arow][ak + 8] = ra[1];
    *(uint4*)&sB[arow][ak]     = rb[0];
    *(uint4*)&sB[arow][ak + 8] = rb[1];
    __syncthreads();
    if (k0 + 32 < 2*HID){
      int k = k0 + 32 + ak;
      const __half* srcA = (k < HID) ? (g_FF16 + offF[arow] + k)
                                     : (g_FB16 + offB[arow] + k - HID);
      ra[0] = *(const uint4*)srcA;
      ra[1] = *(const uint4*)(srcA + 8);
      const __half* srcB = g_WO16 + (size_t)(bn + arow)*(2*HID) + k0 + 32 + ak;
      rb[0] = *(const uint4*)srcB;
      rb[1] = *(const uint4*)(srcB + 8);
    }
    #pragma unroll
    for (int ks = 0; ks < 32; ks += 16){
      uint32_t a[4][4], bq[2][4];
      #pragma unroll
      for (int mt = 0; mt < 4; mt++)
        ldsm4(a[mt], sAu + aOff + (uint32_t)mt*16*80 + (uint32_t)ks*2);
      ldsm4(bq[0], sBu + bOff + (uint32_t)ks*2);
      ldsm4(bq[1], sBu + bOff + 16*80 + (uint32_t)ks*2);
      #pragma unroll
      for (int mt = 0; mt < 4; mt++)
        #pragma unroll
        for (int nt = 0; nt < 4; nt++)
          mma16h(acc[mt][nt], a[mt], &bq[nt>>1][(nt&1)*2]);
    }
  }
  // epilogue: + cnt * bias
  #pragma unroll
  for (int mt = 0; mt < 4; mt++){
    int r0 = warpM*64 + mt*16 + g;
    int gm0 = bm + r0;
    float c0 = (float)cnt[r0], c1 = (float)cnt[r0+8];
    #pragma unroll
    for (int nt = 0; nt < 4; nt++){
      int gn = bn + warpN*32 + nt*8 + 2*t4;
      float bb0 = bout[gn], bb1 = bout[gn+1];
      if (gm0 < MROWS){
        out[(size_t)gm0*NOUT + gn]     = acc[mt][nt][0] + c0*bb0;
        out[(size_t)gm0*NOUT + gn + 1] = acc[mt][nt][1] + c0*bb1;
      }
      if (gm0 + 8 < MROWS){
        out[(size_t)(gm0+8)*NOUT + gn]     = acc[mt][nt][2] + c1*bb0;
        out[(size_t)(gm0+8)*NOUT + gn + 1] = acc[mt][nt][3] + c1*bb1;
      }
    }
  }
}

// ---------------- L2 normalize groups of 256 ----------------
__global__ void normalize_kernel(float* __restrict__ out)
{
  int w = blockIdx.x*8 + (threadIdx.x >> 5);
  int lane = threadIdx.x & 31;
  size_t base = (size_t)w*SEM;
  float v[8]; float ss = 0.f;
  #pragma unroll
  for (int i = 0; i < 8; i++){ v[i] = out[base + lane + 32*i]; ss += v[i]*v[i]; }
  #pragma unroll
  for (int o = 16; o; o >>= 1) ss += __shfl_xor_sync(0xffffffffu, ss, o);
  float sc = 1.f / fmaxf(sqrtf(ss), 1e-12f);
  #pragma unroll
  for (int i = 0; i < 8; i++) out[base + lane + 32*i] = v[i]*sc;
}

// ---------------- launcher ----------------
extern "C" void kernel_launch(void* const* d_in, const int* in_sizes, int n_in,
                              void* d_out, int out_size)
{
  const int*   captions = (const int*)  d_in[1];
  const int*   lengths  = (const int*)  d_in[2];
  const float* emb      = (const float*)d_in[3];
  const float* w_ih_f   = (const float*)d_in[4];
  const float* w_hh_f   = (const float*)d_in[5];
  const float* b_ih_f   = (const float*)d_in[6];
  const float* b_hh_f   = (const float*)d_in[7];
  const float* w_ih_b   = (const float*)d_in[8];
  const float* w_hh_b   = (const float*)d_in[9];
  const float* b_ih_b   = (const float*)d_in[10];
  const float* b_hh_b   = (const float*)d_in[11];
  const float* w_out    = (const float*)d_in[12];
  const float* b_out    = (const float*)d_in[13];
  float* out = (float*)d_out;

  float *wv, *Xf, *Xb;
  cudaGetSymbolAddress((void**)&wv, g_wv);
  cudaGetSymbolAddress((void**)&Xf, g_X);
  Xb = Xf + BSZ*NSEQ*G4;

  zero_state_kernel<<<(4*SB + 255)/256, 256>>>();
  setup_pairs_kernel<<<1, 256>>>();
  embed_kernel<<<BSZ*NSEQ, 256>>>(captions, lengths, emb);
  whh16_kernel<<<(G4*HID + 255)/256, 256>>>(w_hh_f, w_hh_b);
  wout16_kernel<<<(NOUT*2*HID + 255)/256, 256>>>(w_out);

  gemm3x_bias<<<dim3(G4/128, (BSZ*NSEQ + 63)/64), 256>>>(
      wv, w_ih_f, b_ih_f, b_hh_f, Xf, BSZ*NSEQ, G4, DIM);
  gemm3x_bias<<<dim3(G4/128, (BSZ*NSEQ + 63)/64), 256>>>(
      wv, w_ih_b, b_ih_b, b_hh_b, Xb, BSZ*NSEQ, G4, DIM);

  for (int j = 0; j < NSEQ; j++)
    lstm_fused<<<dim3(HID/64, 10, 2), 256>>>(j);

  out_gemm_fp16<<<dim3(NOUT/128, (MROWS + 127)/128), 256>>>(b_out, out);
  normalize_kernel<<<(MROWS*30)/8, 256>>>(out);
}

// round 10
// speedup vs baseline: 5.9535x; 1.0866x over previous
#include <cuda_runtime.h>
#include <cuda_fp16.h>
#include <stdint.h>

#define BSZ 32
#define NSEQ 20
#define DIM 512
#define HID 512
#define G4 2048          // 4*HID
#define NOUT 7680        // NT*SEM
#define SEM 256
#define NPAIR 190
#define MROWS (BSZ*NPAIR)   // 6080
#define SB (NSEQ*BSZ*HID)   // 640*512 per plane
#define FSZ (BSZ*NSEQ*NSEQ*HID)
#define LSTM_BLOCKS 88

// ---------------- device scratch ----------------
__device__ __half g_WV16[BSZ*NSEQ*DIM];        // masked word vectors fp16
__device__ float g_X[2][BSZ*NSEQ*G4];          // input projections (f, b)
__device__ __half g_H16[2][2][SB];             // [dir][parity] hidden (fp16)
__device__ float g_C[2][SB];                   // cell state
__device__ __half g_WI16[2][G4*DIM];           // W_ih fp16 (f, b)
__device__ __half g_W16[2][G4*HID];            // W_hh fp16 (f, b)
__device__ float g_Ff[FSZ];                    // fp32 cumulative sums
__device__ float g_Fb[FSZ];
__device__ __half g_FF16[FSZ];                 // fp16 cumsum planes (out GEMM)
__device__ __half g_FB16[FSZ];
__device__ __half g_WO16[NOUT*2*HID];          // fp16 w_out
__device__ int   g_psF[NPAIR];
__device__ int   g_psB[NPAIR];
__device__ int   g_pcnt[NPAIR];
__device__ unsigned g_bar;

__device__ __forceinline__ float sigm(float x){ return 1.f/(1.f+__expf(-x)); }

__device__ __forceinline__ void mma16h(float c[4], const uint32_t a[4], const uint32_t b[2]){
  asm volatile("mma.sync.aligned.m16n8k16.row.col.f32.f16.f16.f32 "
      "{%0,%1,%2,%3}, {%4,%5,%6,%7}, {%8,%9}, {%0,%1,%2,%3};\n"
      : "+f"(c[0]), "+f"(c[1]), "+f"(c[2]), "+f"(c[3])
      : "r"(a[0]), "r"(a[1]), "r"(a[2]), "r"(a[3]), "r"(b[0]), "r"(b[1]));
}
__device__ __forceinline__ void ldsm4(uint32_t r[4], uint32_t saddr){
  asm volatile("ldmatrix.sync.aligned.m8n8.x4.shared.b16 {%0,%1,%2,%3}, [%4];"
      : "=r"(r[0]), "=r"(r[1]), "=r"(r[2]), "=r"(r[3]) : "r"(saddr));
}

// ---------------- small setup kernels ----------------
__global__ void zero_state_kernel(){
  int i = blockIdx.x*blockDim.x + threadIdx.x;
  if (i < 4*SB) (&g_H16[0][0][0])[i] = __float2half(0.f);
  if (i < 2*SB) (&g_C[0][0])[i] = 0.f;
}

// convert W_ih and W_hh (both dirs) to fp16; 2048x512 each
__global__ void wconv_kernel(const float* __restrict__ wih_f, const float* __restrict__ wih_b,
                             const float* __restrict__ whh_f, const float* __restrict__ whh_b){
  int i = blockIdx.x*blockDim.x + threadIdx.x;
  if (i >= G4*HID) return;
  g_WI16[0][i] = __float2half(wih_f[i]);
  g_WI16[1][i] = __float2half(wih_b[i]);
  g_W16[0][i]  = __float2half(whh_f[i]);
  g_W16[1][i]  = __float2half(whh_b[i]);
}

__global__ void wout16_kernel(const float* __restrict__ w){
  int i = blockIdx.x*blockDim.x + threadIdx.x;
  if (i < NOUT*2*HID) g_WO16[i] = __float2half(w[i]);
}

__global__ void setup_pairs_kernel(){
  if (threadIdx.x == 0) g_bar = 0;           // reset grid barrier each replay
  int p = threadIdx.x;
  if (p >= NPAIR) return;
  int cum = 0, k = 1, s = 0;
  for (int kk = 1; kk < NSEQ; kk++){
    int c = NSEQ - kk;
    if (p < cum + c){ k = kk; s = p - cum; break; }
    cum += c;
  }
  int e = s + k;
  g_psF[p] = s*NSEQ + e;
  g_psB[p] = e*NSEQ + s;
  g_pcnt[p] = k + 1;
}

__global__ void embed_kernel(const int* __restrict__ cap, const int* __restrict__ len,
                             const float* __restrict__ emb){
  int bt = blockIdx.x; int b = bt/NSEQ, t = bt%NSEQ;
  int tok = cap[bt];
  float m = (t < len[b]) ? 1.f : 0.f;
  const float* src = emb + (size_t)tok*DIM;
  for (int n = threadIdx.x; n < DIM; n += blockDim.x)
    g_WV16[bt*DIM + n] = __float2half(m * src[n]);
}

// =======================================================================
// FP16 projection GEMM: X[dir] = WV16 @ WI16[dir]^T + (b_ih + b_hh)
// M=640, N=2048, K=512. BM=BN=128, BK=32, 256 thr. grid (16, 5, 2)
// =======================================================================
__global__ __launch_bounds__(256) void gemm16_bias(
    const float* __restrict__ bif, const float* __restrict__ bhf,
    const float* __restrict__ bib, const float* __restrict__ bhb)
{
  const int dir = blockIdx.z;
  const __half* __restrict__ A = g_WV16;
  const __half* __restrict__ B = g_WI16[dir];
  const float* __restrict__ b1 = dir ? bib : bif;
  const float* __restrict__ b2 = dir ? bhb : bhf;
  float* __restrict__ C = g_X[dir];

  __shared__ __align__(16) __half sA[128][40];
  __shared__ __align__(16) __half sB[128][40];
  const int tid = threadIdx.x, lane = tid & 31, wid = tid >> 5;
  const int warpM = wid >> 2, warpN = wid & 3;
  const int g = lane >> 2, t4 = lane & 3;
  const int bm = blockIdx.y*128, bn = blockIdx.x*128;

  const uint32_t sAu = (uint32_t)__cvta_generic_to_shared(&sA[0][0]);
  const uint32_t sBu = (uint32_t)__cvta_generic_to_shared(&sB[0][0]);
  const int bmat = lane >> 3;
  const uint32_t aOff = ((uint32_t)(warpM*64 + (lane & 15))*40 + (uint32_t)(lane >> 4)*8)*2;
  const uint32_t bOff = ((uint32_t)(warpN*32 + ((bmat >> 1)*8) + (lane & 7))*40
                        + (uint32_t)(bmat & 1)*8)*2;

  const int arow = tid >> 1, ak = (tid & 1)*16;
  uint4 ra[2], rb[2];
  {
    const __half* srcA = A + (size_t)(bm + arow)*DIM + ak;
    ra[0] = *(const uint4*)srcA;
    ra[1] = *(const uint4*)(srcA + 8);
    const __half* srcB = B + (size_t)(bn + arow)*DIM + ak;
    rb[0] = *(const uint4*)srcB;
    rb[1] = *(const uint4*)(srcB + 8);
  }

  float acc[4][4][4] = {};
  for (int k0 = 0; k0 < DIM; k0 += 32){
    __syncthreads();
    *(uint4*)&sA[arow][ak]     = ra[0];
    *(uint4*)&sA[arow][ak + 8] = ra[1];
    *(uint4*)&sB[arow][ak]     = rb[0];
    *(uint4*)&sB[arow][ak + 8] = rb[1];
    __syncthreads();
    if (k0 + 32 < DIM){
      const __half* srcA = A + (size_t)(bm + arow)*DIM + k0 + 32 + ak;
      ra[0] = *(const uint4*)srcA;
      ra[1] = *(const uint4*)(srcA + 8);
      const __half* srcB = B + (size_t)(bn + arow)*DIM + k0 + 32 + ak;
      rb[0] = *(const uint4*)srcB;
      rb[1] = *(const uint4*)(srcB + 8);
    }
    #pragma unroll
    for (int ks = 0; ks < 32; ks += 16){
      uint32_t a[4][4], bq[2][4];
      #pragma unroll
      for (int mt = 0; mt < 4; mt++)
        ldsm4(a[mt], sAu + aOff + (uint32_t)mt*16*80 + (uint32_t)ks*2);
      ldsm4(bq[0], sBu + bOff + (uint32_t)ks*2);
      ldsm4(bq[1], sBu + bOff + 16*80 + (uint32_t)ks*2);
      #pragma unroll
      for (int mt = 0; mt < 4; mt++)
        #pragma unroll
        for (int nt = 0; nt < 4; nt++)
          mma16h(acc[mt][nt], a[mt], &bq[nt>>1][(nt&1)*2]);
    }
  }
  #pragma unroll
  for (int mt = 0; mt < 4; mt++){
    int gm0 = bm + warpM*64 + mt*16 + g;
    #pragma unroll
    for (int nt = 0; nt < 4; nt++){
      int gn = bn + warpN*32 + nt*8 + 2*t4;
      float e0 = b1[gn] + b2[gn], e1 = b1[gn+1] + b2[gn+1];
      C[(size_t)gm0*G4 + gn]         = acc[mt][nt][0] + e0;
      C[(size_t)gm0*G4 + gn + 1]     = acc[mt][nt][1] + e1;
      C[(size_t)(gm0+8)*G4 + gn]     = acc[mt][nt][2] + e0;
      C[(size_t)(gm0+8)*G4 + gn + 1] = acc[mt][nt][3] + e1;
    }
  }
}

// =======================================================================
// Persistent LSTM: all 20 steps in ONE kernel, 88 blocks, grid barrier.
// Per step: exactly 88 tiles = 8 n-tiles x (ceil((j+1)/2) fwd + ceil((20-j)/2) bwd).
// =======================================================================
__device__ __forceinline__ void grid_sync(unsigned target){
  __syncthreads();
  if (threadIdx.x == 0){
    __threadfence();
    atomicAdd(&g_bar, 1u);
    while (atomicAdd(&g_bar, 0u) < target) {}
    __threadfence();
  }
  __syncthreads();
}

__global__ __launch_bounds__(256) void lstm_persist()
{
  const int n0 = (blockIdx.x & 7) * 64;
  const int rt = blockIdx.x >> 3;            // 0..10
  const int tid = threadIdx.x, lane = tid & 31, wid = tid >> 5;
  const int warpM = wid & 3, warpN = wid >> 2;
  const int g8 = lane >> 2, t4 = lane & 3;

  __shared__ __align__(16) uint16_t sA[64][24];    // 3072 B
  __shared__ __align__(16) uint16_t sB[256][24];   // 12288 B
  const uint32_t sAu = (uint32_t)__cvta_generic_to_shared(&sA[0][0]);
  const uint32_t sBu = (uint32_t)__cvta_generic_to_shared(&sB[0][0]);
  const int bmat = lane >> 3;
  const uint32_t aOff = ((uint32_t)(warpM*16 + (lane & 15))*24 + (uint32_t)(lane >> 4)*8)*2;
  const uint32_t bOff = ((uint32_t)(warpN*32 + ((bmat >> 1)*8) + (lane & 7))*24
                        + (uint32_t)(bmat & 1)*8)*2;
  const int arow = tid >> 1, ak8 = (tid & 1)*8;

  for (int j = 0; j < NSEQ; j++){
    const int p = j & 1;
    const int tf = (j + 2) >> 1;             // ceil((j+1)/2) forward tiles
    int dir, bm, rowLim;
    if (rt < tf){ dir = 0; bm = rt*64;                   rowLim = (j+1)*BSZ; }
    else        { dir = 1; bm = j*BSZ + (rt - tf)*64;    rowLim = NSEQ*BSZ; }

    const __half* __restrict__ Ain = g_H16[dir][p];
    const __half* __restrict__ W = g_W16[dir];

    float acc[4][4][4] = {};
    uint4 ra; uint4 rb[2];
    {
      int gr = bm + arow;
      if (tid < 128)
        ra = (gr < rowLim) ? *(const uint4*)(Ain + (size_t)gr*HID + ak8)
                           : make_uint4(0,0,0,0);
      #pragma unroll
      for (int s = 0; s < 2; s++){
        int i = tid + s*256;
        int rbr = i >> 1, k8 = (i & 1)*8;
        int wrow = (rbr >> 6)*HID + n0 + (rbr & 63);
        rb[s] = *(const uint4*)(W + (size_t)wrow*HID + k8);
      }
    }

    for (int k0 = 0; k0 < HID; k0 += 16){
      __syncthreads();
      if (tid < 128) *(uint4*)&sA[arow][ak8] = ra;
      #pragma unroll
      for (int s = 0; s < 2; s++){
        int i = tid + s*256;
        int rbr = i >> 1, k8 = (i & 1)*8;
        *(uint4*)&sB[rbr][k8] = rb[s];
      }
      __syncthreads();
      if (k0 + 16 < HID){
        int kn = k0 + 16;
        if (tid < 128){
          int gr = bm + arow;
          ra = (gr < rowLim) ? *(const uint4*)(Ain + (size_t)gr*HID + kn + ak8)
                             : make_uint4(0,0,0,0);
        }
        #pragma unroll
        for (int s = 0; s < 2; s++){
          int i = tid + s*256;
          int rbr = i >> 1, k8 = (i & 1)*8;
          int wrow = (rbr >> 6)*HID + n0 + (rbr & 63);
          rb[s] = *(const uint4*)(W + (size_t)wrow*HID + kn + k8);
        }
      }
      uint32_t af[4];
      ldsm4(af, sAu + aOff);
      #pragma unroll
      for (int g = 0; g < 4; g++){
        uint32_t bq[2][4];
        uint32_t base = sBu + (uint32_t)g*64*48 + bOff;
        ldsm4(bq[0], base);
        ldsm4(bq[1], base + 16*48);
        #pragma unroll
        for (int nt = 0; nt < 4; nt++)
          mma16h(acc[g][nt], af, &bq[nt>>1][(nt&1)*2]);
      }
    }

    // ---- epilogue: gates -> c,h -> state + cumulative F ----
    {
      const float* __restrict__ X = g_X[dir];
      float* __restrict__ C = g_C[dir];
      __half* __restrict__ Hn = g_H16[dir][p^1];
      float* __restrict__ F  = dir ? g_Fb  : g_Ff;
      __half* __restrict__ F16 = dir ? g_FB16 : g_FF16;

      #pragma unroll
      for (int rr = 0; rr < 2; rr++){
        int gm = bm + warpM*16 + g8 + rr*8;
        if (gm >= rowLim) continue;
        int chain = gm >> 5, b = gm & 31;
        int t = dir ? (chain - j) : j;
        size_t xrow = (size_t)(b*NSEQ + t)*G4;
        size_t fbase;
        bool first;
        if (dir == 0){ fbase = ((size_t)(b*NSEQ + chain)*NSEQ + j)*HID; first = (j == chain); }
        else         { fbase = ((size_t)(b*NSEQ + chain)*NSEQ + t)*HID; first = (t == chain); }
        #pragma unroll
        for (int nt = 0; nt < 4; nt++){
          #pragma unroll
          for (int cc = 0; cc < 2; cc++){
            int n = n0 + warpN*32 + nt*8 + t4*2 + cc;
            int ai = rr*2 + cc;
            float gi = acc[0][nt][ai] + X[xrow + n];
            float gf = acc[1][nt][ai] + X[xrow + 512 + n];
            float gc = acc[2][nt][ai] + X[xrow + 1024 + n];
            float go = acc[3][nt][ai] + X[xrow + 1536 + n];
            size_t si = (size_t)gm*HID + n;
            float c = sigm(gf)*C[si] + sigm(gi)*tanhf(gc);
            float h = sigm(go)*tanhf(c);
            C[si] = c;
            Hn[si] = __float2half(h);
            float prev = first ? 0.f : F[fbase + n + (dir ? (int)HID : -(int)HID)];
            float v = prev + h;
            F[fbase + n]   = v;
            F16[fbase + n] = __float2half(v);
          }
        }
      }
    }
    grid_sync((unsigned)(LSTM_BLOCKS*(j+1)));
  }
}

// =======================================================================
// out GEMM: single-pass FP16 m16n8k16 with ldmatrix frags (unchanged R8/R9).
// =======================================================================
__global__ __launch_bounds__(256) void out_gemm_fp16(const float* __restrict__ bout,
                                                     float* __restrict__ out)
{
  __shared__ __align__(16) __half sA[128][40];
  __shared__ __align__(16) __half sB[128][40];
  __shared__ int offF[128], offB[128], cnt[128];
  const int tid = threadIdx.x, lane = tid & 31, wid = tid >> 5;
  const int warpM = wid >> 2, warpN = wid & 3;
  const int g = lane >> 2, t4 = lane & 3;
  const int bm = blockIdx.y*128, bn = blockIdx.x*128;

  if (tid < 128){
    int gm = bm + tid;
    if (gm < MROWS){
      int b = gm / NPAIR, p = gm % NPAIR;
      offF[tid] = (b*NSEQ*NSEQ + g_psF[p])*HID;
      offB[tid] = (b*NSEQ*NSEQ + g_psB[p])*HID;
      cnt[tid]  = g_pcnt[p];
    } else { offF[tid] = 0; offB[tid] = 0; cnt[tid] = 0; }
  }
  __syncthreads();

  const uint32_t sAu = (uint32_t)__cvta_generic_to_shared(&sA[0][0]);
  const uint32_t sBu = (uint32_t)__cvta_generic_to_shared(&sB[0][0]);
  const int bmat = lane >> 3;
  const uint32_t aOff = ((uint32_t)(warpM*64 + (lane & 15))*40 + (uint32_t)(lane >> 4)*8)*2;
  const uint32_t bOff = ((uint32_t)(warpN*32 + ((bmat >> 1)*8) + (lane & 7))*40
                        + (uint32_t)(bmat & 1)*8)*2;

  const int arow = tid >> 1, ak = (tid & 1)*16;
  uint4 ra[2], rb[2];
  {
    const __half* srcA = g_FF16 + offF[arow] + ak;
    ra[0] = *(const uint4*)srcA;
    ra[1] = *(const uint4*)(srcA + 8);
    const __half* srcB = g_WO16 + (size_t)(bn + arow)*(2*HID) + ak;
    rb[0] = *(const uint4*)srcB;
    rb[1] = *(const uint4*)(srcB + 8);
  }

  float acc[4][4][4] = {};
  for (int k0 = 0; k0 < 2*HID; k0 += 32){
    __syncthreads();
    *(uint4*)&sA[arow][ak]     = ra[0];
    *(uint4*)&sA[arow][ak + 8] = ra[1];
    *(uint4*)&sB[arow][ak]     = rb[0];
    *(uint4*)&sB[arow][ak + 8] = rb[1];
    __syncthreads();
    if (k0 + 32 < 2*HID){
      int k = k0 + 32 + ak;
      const __half* srcA = (k < HID) ? (g_FF16 + offF[arow] + k)
                                     : (g_FB16 + offB[arow] + k - HID);
      ra[0] = *(const uint4*)srcA;
      ra[1] = *(const uint4*)(srcA + 8);
      const __half* srcB = g_WO16 + (size_t)(bn + arow)*(2*HID) + k0 + 32 + ak;
      rb[0] = *(const uint4*)srcB;
      rb[1] = *(const uint4*)(srcB + 8);
    }
    #pragma unroll
    for (int ks = 0; ks < 32; ks += 16){
      uint32_t a[4][4], bq[2][4];
      #pragma unroll
      for (int mt = 0; mt < 4; mt++)
        ldsm4(a[mt], sAu + aOff + (uint32_t)mt*16*80 + (uint32_t)ks*2);
      ldsm4(bq[0], sBu + bOff + (uint32_t)ks*2);
      ldsm4(bq[1], sBu + bOff + 16*80 + (uint32_t)ks*2);
      #pragma unroll
      for (int mt = 0; mt < 4; mt++)
        #pragma unroll
        for (int nt = 0; nt < 4; nt++)
          mma16h(acc[mt][nt], a[mt], &bq[nt>>1][(nt&1)*2]);
    }
  }
  // epilogue: + cnt * bias
  #pragma unroll
  for (int mt = 0; mt < 4; mt++){
    int r0 = warpM*64 + mt*16 + g;
    int gm0 = bm + r0;
    float c0 = (float)cnt[r0], c1 = (float)cnt[r0+8];
    #pragma unroll
    for (int nt = 0; nt < 4; nt++){
      int gn = bn + warpN*32 + nt*8 + 2*t4;
      float bb0 = bout[gn], bb1 = bout[gn+1];
      if (gm0 < MROWS){
        out[(size_t)gm0*NOUT + gn]     = acc[mt][nt][0] + c0*bb0;
        out[(size_t)gm0*NOUT + gn + 1] = acc[mt][nt][1] + c0*bb1;
      }
      if (gm0 + 8 < MROWS){
        out[(size_t)(gm0+8)*NOUT + gn]     = acc[mt][nt][2] + c1*bb0;
        out[(size_t)(gm0+8)*NOUT + gn + 1] = acc[mt][nt][3] + c1*bb1;
      }
    }
  }
}

// ---------------- L2 normalize groups of 256 ----------------
__global__ void normalize_kernel(float* __restrict__ out)
{
  int w = blockIdx.x*8 + (threadIdx.x >> 5);
  int lane = threadIdx.x & 31;
  size_t base = (size_t)w*SEM;
  float v[8]; float ss = 0.f;
  #pragma unroll
  for (int i = 0; i < 8; i++){ v[i] = out[base + lane + 32*i]; ss += v[i]*v[i]; }
  #pragma unroll
  for (int o = 16; o; o >>= 1) ss += __shfl_xor_sync(0xffffffffu, ss, o);
  float sc = 1.f / fmaxf(sqrtf(ss), 1e-12f);
  #pragma unroll
  for (int i = 0; i < 8; i++) out[base + lane + 32*i] = v[i]*sc;
}

// ---------------- launcher ----------------
extern "C" void kernel_launch(void* const* d_in, const int* in_sizes, int n_in,
                              void* d_out, int out_size)
{
  const int*   captions = (const int*)  d_in[1];
  const int*   lengths  = (const int*)  d_in[2];
  const float* emb      = (const float*)d_in[3];
  const float* w_ih_f   = (const float*)d_in[4];
  const float* w_hh_f   = (const float*)d_in[5];
  const float* b_ih_f   = (const float*)d_in[6];
  const float* b_hh_f   = (const float*)d_in[7];
  const float* w_ih_b   = (const float*)d_in[8];
  const float* w_hh_b   = (const float*)d_in[9];
  const float* b_ih_b   = (const float*)d_in[10];
  const float* b_hh_b   = (const float*)d_in[11];
  const float* w_out    = (const float*)d_in[12];
  const float* b_out    = (const float*)d_in[13];
  float* out = (float*)d_out;

  zero_state_kernel<<<(4*SB + 255)/256, 256>>>();
  setup_pairs_kernel<<<1, 256>>>();
  embed_kernel<<<BSZ*NSEQ, 256>>>(captions, lengths, emb);
  wconv_kernel<<<(G4*HID + 255)/256, 256>>>(w_ih_f, w_ih_b, w_hh_f, w_hh_b);
  wout16_kernel<<<(NOUT*2*HID + 255)/256, 256>>>(w_out);

  // input projections (single-pass fp16, both dirs)
  gemm16_bias<<<dim3(G4/128, (BSZ*NSEQ)/128, 2), 256>>>(b_ih_f, b_hh_f, b_ih_b, b_hh_b);

  // all 20 LSTM steps in one persistent kernel
  lstm_persist<<<LSTM_BLOCKS, 256>>>();

  out_gemm_fp16<<<dim3(NOUT/128, (MROWS + 127)/128), 256>>>(b_out, out);
  normalize_kernel<<<(MROWS*30)/8, 256>>>(out);
}